// round 12
// baseline (speedup 1.0000x reference)
#include <cuda_runtime.h>
#include <cstdint>
#include <math.h>

#define NN   50000
#define NE   600000
#define HD   128
#define NREL 3
#define OUTD 40
#define NB   (NREL * NN)          // (dst,type) buckets

// SMEM strides (floats) for conflict-free mma fragment loads:
#define SMA_STRIDE 132
#define SMB_STRIDE 136
#define MMA_SMEM4 ((128 * SMA_STRIDE + 2 * 128 * SMB_STRIDE) * 4)
#define MMA_SMEM1 ((128 * SMA_STRIDE + 128 * SMB_STRIDE) * 4)

// ---------------- scratch (device globals; no allocation) ----------------
static __device__ float g_H [(size_t)NREL * NN * HD];
static __device__ float g_A [(size_t)NN * HD];
static __device__ float g_X1[(size_t)NN * HD];
static __device__ float g_X2[(size_t)NN * HD];
static __device__ float g_H3[(size_t)NN * HD];
static __device__ float g_H4[(size_t)NN * 64];
static __device__ int      g_rowptr[NB + 1];
static __device__ int      g_cur[NB];
static __device__ unsigned g_csr[NE];     // src (type implied by segment)

// ---------------- helpers ----------------
__device__ __forceinline__ float wsum(float v) {
    #pragma unroll
    for (int o = 16; o > 0; o >>= 1) v += __shfl_xor_sync(0xFFFFFFFFu, v, o);
    return v;
}
__device__ __forceinline__ float hsum16(float v) {
    #pragma unroll
    for (int o = 8; o > 0; o >>= 1) v += __shfl_xor_sync(0xFFFFFFFFu, v, o);
    return v;
}
__device__ __forceinline__ float hmax16(float v) {
    #pragma unroll
    for (int o = 8; o > 0; o >>= 1) v = fmaxf(v, __shfl_xor_sync(0xFFFFFFFFu, v, o));
    return v;
}
__device__ __forceinline__ float to_tf32(float x) {
    unsigned r;
    asm("cvt.rna.tf32.f32 %0, %1;" : "=r"(r) : "f"(x));
    return __uint_as_float(r);
}
__device__ __forceinline__ void mma_tf32(float* c, const unsigned* a, const unsigned* b) {
    asm volatile(
        "mma.sync.aligned.m16n8k8.row.col.f32.tf32.tf32.f32 "
        "{%0,%1,%2,%3}, {%4,%5,%6,%7}, {%8,%9}, {%0,%1,%2,%3};"
        : "+f"(c[0]), "+f"(c[1]), "+f"(c[2]), "+f"(c[3])
        : "r"(a[0]), "r"(a[1]), "r"(a[2]), "r"(a[3]), "r"(b[0]), "r"(b[1]));
}

// ================= MMA GEMM pieces (512 threads / 16 warps) =================
__device__ __forceinline__ void stage_A(const float* __restrict__ A, float* As,
                                        int row0, int N, int tid) {
    #pragma unroll
    for (int i = 0; i < 8; i++) {
        int idx = i * 512 + tid;
        int r = idx >> 5, c4 = (idx & 31) * 4;
        float4 v = make_float4(0.f, 0.f, 0.f, 0.f);
        if (row0 + r < N) v = *(const float4*)&A[(size_t)(row0 + r) * 128 + c4];
        v.x = to_tf32(v.x); v.y = to_tf32(v.y);
        v.z = to_tf32(v.z); v.w = to_tf32(v.w);
        *(float4*)&As[r * SMA_STRIDE + c4] = v;
    }
}
__device__ __forceinline__ void stage_B(const float* __restrict__ B, float* Bs, int tid) {
    #pragma unroll
    for (int i = 0; i < 8; i++) {
        int idx = i * 512 + tid;
        int k = idx >> 5, c4 = (idx & 31) * 4;
        float4 v = *(const float4*)&B[(size_t)k * 128 + c4];
        v.x = to_tf32(v.x); v.y = to_tf32(v.y);
        v.z = to_tf32(v.z); v.w = to_tf32(v.w);
        *(float4*)&Bs[k * SMB_STRIDE + c4] = v;
    }
}
__device__ __forceinline__ void copy_B_async(const float* __restrict__ B, float* Bs, int tid) {
    unsigned base = (unsigned)__cvta_generic_to_shared(Bs);
    #pragma unroll
    for (int i = 0; i < 8; i++) {
        int idx = i * 512 + tid;
        int k = idx >> 5, c4 = (idx & 31) * 4;
        asm volatile("cp.async.cg.shared.global [%0], [%1], 16;" ::
            "r"(base + (unsigned)((k * SMB_STRIDE + c4) * 4)),
            "l"(B + (size_t)k * 128 + c4) : "memory");
    }
}
__device__ __forceinline__ void acc_zero(float acc[2][4][4]) {
    #pragma unroll
    for (int mt = 0; mt < 2; mt++)
        #pragma unroll
        for (int nt = 0; nt < 4; nt++)
            #pragma unroll
            for (int q = 0; q < 4; q++) acc[mt][nt][q] = 0.f;
}
__device__ __forceinline__ void mma_compute_core(const float* As, const float* Bs,
                                                 int lane, int wm, int wn,
                                                 float acc[2][4][4], bool cvtB) {
    const float* Ab = As + (wm * 32 + (lane >> 2)) * SMA_STRIDE + (lane & 3);
    const float* Bb = Bs + (lane & 3) * SMB_STRIDE + wn * 32 + (lane >> 2);
    #pragma unroll
    for (int ks = 0; ks < 16; ks++) {
        unsigned a[2][4], b[4][2];
        #pragma unroll
        for (int mt = 0; mt < 2; mt++) {
            const float* p = Ab + mt * (16 * SMA_STRIDE) + ks * 8;
            a[mt][0] = __float_as_uint(p[0]);
            a[mt][1] = __float_as_uint(p[8 * SMA_STRIDE]);
            a[mt][2] = __float_as_uint(p[4]);
            a[mt][3] = __float_as_uint(p[8 * SMA_STRIDE + 4]);
        }
        #pragma unroll
        for (int nt = 0; nt < 4; nt++) {
            const float* p = Bb + ks * (8 * SMB_STRIDE) + nt * 8;
            if (cvtB) {
                b[nt][0] = __float_as_uint(to_tf32(p[0]));
                b[nt][1] = __float_as_uint(to_tf32(p[4 * SMB_STRIDE]));
            } else {
                b[nt][0] = __float_as_uint(p[0]);
                b[nt][1] = __float_as_uint(p[4 * SMB_STRIDE]);
            }
        }
        #pragma unroll
        for (int mt = 0; mt < 2; mt++)
            #pragma unroll
            for (int nt = 0; nt < 4; nt++)
                mma_tf32(acc[mt][nt], a[mt], b[nt]);
    }
}
__device__ __forceinline__ void mma_epilogue(float acc[2][4][4],
                                             const float* __restrict__ bias,
                                             float* __restrict__ C,
                                             int row0, int N, int lane, int wm, int wn) {
    #pragma unroll
    for (int nt = 0; nt < 4; nt++) {
        int c = wn * 32 + nt * 8 + (lane & 3) * 2;
        float b0 = bias ? bias[c] : 0.f;
        float b1 = bias ? bias[c + 1] : 0.f;
        #pragma unroll
        for (int mt = 0; mt < 2; mt++) {
            int r = row0 + wm * 32 + mt * 16 + (lane >> 2);
            float2 v0, v1;
            v0.x = acc[mt][nt][0] + b0; v0.y = acc[mt][nt][1] + b1;
            v1.x = acc[mt][nt][2] + b0; v1.y = acc[mt][nt][3] + b1;
            if (r < N)     *(float2*)&C[(size_t)r * 128 + c]       = v0;
            if (r + 8 < N) *(float2*)&C[(size_t)(r + 8) * 128 + c] = v1;
        }
    }
}
__device__ __forceinline__ void mma_ln_act_epilogue(
    float acc[2][4][4], float* sm,
    const float* __restrict__ bias, const float* __restrict__ lg,
    const float* __restrict__ lb, float* __restrict__ C,
    int row0, int N, int lane, int wm, int wn, int act)
{
    float bc[4][2];
    #pragma unroll
    for (int nt = 0; nt < 4; nt++) {
        int c = wn * 32 + nt * 8 + (lane & 3) * 2;
        bc[nt][0] = bias[c]; bc[nt][1] = bias[c + 1];
    }
    float psA[2], pqA[2], psB[2], pqB[2];
    #pragma unroll
    for (int mt = 0; mt < 2; mt++) {
        float sA = 0.f, qA = 0.f, sB = 0.f, qB = 0.f;
        #pragma unroll
        for (int nt = 0; nt < 4; nt++) {
            float v0 = acc[mt][nt][0] + bc[nt][0];
            float v1 = acc[mt][nt][1] + bc[nt][1];
            float v2 = acc[mt][nt][2] + bc[nt][0];
            float v3 = acc[mt][nt][3] + bc[nt][1];
            sA += v0 + v1; qA += v0 * v0 + v1 * v1;
            sB += v2 + v3; qB += v2 * v2 + v3 * v3;
        }
        #pragma unroll
        for (int o = 1; o < 4; o <<= 1) {
            sA += __shfl_xor_sync(0xFFFFFFFFu, sA, o);
            qA += __shfl_xor_sync(0xFFFFFFFFu, qA, o);
            sB += __shfl_xor_sync(0xFFFFFFFFu, sB, o);
            qB += __shfl_xor_sync(0xFFFFFFFFu, qB, o);
        }
        psA[mt] = sA; pqA[mt] = qA; psB[mt] = sB; pqB[mt] = qB;
    }
    __syncthreads();
    float* S1 = sm;
    float* S2 = sm + 512;
    if ((lane & 3) == 0) {
        #pragma unroll
        for (int mt = 0; mt < 2; mt++) {
            int rA = wm * 32 + mt * 16 + (lane >> 2);
            S1[rA * 4 + wn] = psA[mt];        S2[rA * 4 + wn] = pqA[mt];
            S1[(rA + 8) * 4 + wn] = psB[mt];  S2[(rA + 8) * 4 + wn] = pqB[mt];
        }
    }
    __syncthreads();
    #pragma unroll
    for (int mt = 0; mt < 2; mt++) {
        int rlA = wm * 32 + mt * 16 + (lane >> 2);
        int rlB = rlA + 8;
        float sA = S1[rlA * 4 + 0] + S1[rlA * 4 + 1] + S1[rlA * 4 + 2] + S1[rlA * 4 + 3];
        float qA = S2[rlA * 4 + 0] + S2[rlA * 4 + 1] + S2[rlA * 4 + 2] + S2[rlA * 4 + 3];
        float sB = S1[rlB * 4 + 0] + S1[rlB * 4 + 1] + S1[rlB * 4 + 2] + S1[rlB * 4 + 3];
        float qB = S2[rlB * 4 + 0] + S2[rlB * 4 + 1] + S2[rlB * 4 + 2] + S2[rlB * 4 + 3];
        float mA = sA * (1.f / HD), mB = sB * (1.f / HD);
        float iA = rsqrtf(qA * (1.f / HD) - mA * mA + 1e-5f);
        float iB = rsqrtf(qB * (1.f / HD) - mB * mB + 1e-5f);
        #pragma unroll
        for (int nt = 0; nt < 4; nt++) {
            int c = wn * 32 + nt * 8 + (lane & 3) * 2;
            float g0 = lg[c], g1 = lg[c + 1], l0 = lb[c], l1 = lb[c + 1];
            float v0 = (acc[mt][nt][0] + bc[nt][0] - mA) * iA * g0 + l0;
            float v1 = (acc[mt][nt][1] + bc[nt][1] - mA) * iA * g1 + l1;
            float v2 = (acc[mt][nt][2] + bc[nt][0] - mB) * iB * g0 + l0;
            float v3 = (acc[mt][nt][3] + bc[nt][1] - mB) * iB * g1 + l1;
            if (act == 0) {
                v0 = fmaxf(v0, 0.f); v1 = fmaxf(v1, 0.f);
                v2 = fmaxf(v2, 0.f); v3 = fmaxf(v3, 0.f);
            } else {
                v0 = 0.5f * v0 * (1.f + erff(v0 * 0.70710678118654752f));
                v1 = 0.5f * v1 * (1.f + erff(v1 * 0.70710678118654752f));
                v2 = 0.5f * v2 * (1.f + erff(v2 * 0.70710678118654752f));
                v3 = 0.5f * v3 * (1.f + erff(v3 * 0.70710678118654752f));
            }
            int r = row0 + wm * 32 + mt * 16 + (lane >> 2);
            if (r < N)     { float2 w = {v0, v1}; *(float2*)&C[(size_t)r * 128 + c] = w; }
            if (r + 8 < N) { float2 w = {v2, v3}; *(float2*)&C[(size_t)(r + 8) * 128 + c] = w; }
        }
    }
}

// ---------------- conv 4-in-1 GEMM (512 threads, cp.async double-buffered B) ----------------
__global__ __launch_bounds__(512) void mma_gemm4_k(
    const float* __restrict__ A, const float* __restrict__ Broot,
    const float* __restrict__ Brel, const float* __restrict__ bias,
    float* __restrict__ Croot, float* __restrict__ Crel, int N)
{
    extern __shared__ float sm[];
    float* As  = sm;
    float* Bs0 = sm + 128 * SMA_STRIDE;
    float* Bs1 = Bs0 + 128 * SMB_STRIDE;

    const int tid  = threadIdx.x;
    const int row0 = blockIdx.x * 128;
    const int lane = tid & 31;
    const int wid  = tid >> 5;
    const int wm   = wid & 3;
    const int wn   = wid >> 2;

    copy_B_async(Broot, Bs0, tid);
    asm volatile("cp.async.commit_group;" ::: "memory");
    copy_B_async(Brel, Bs1, tid);
    asm volatile("cp.async.commit_group;" ::: "memory");
    stage_A(A, As, row0, N, tid);

    float acc[2][4][4];
    #pragma unroll
    for (int r = 0; r < 4; r++) {
        if (r == 3) asm volatile("cp.async.wait_group 0;" ::: "memory");
        else        asm volatile("cp.async.wait_group 1;" ::: "memory");
        __syncthreads();
        const float* Bs = (r & 1) ? Bs1 : Bs0;
        acc_zero(acc);
        mma_compute_core(As, Bs, lane, wm, wn, acc, true);
        float* Cp = (r == 0) ? Croot : Crel + (size_t)(r - 1) * NN * HD;
        mma_epilogue(acc, (r == 0) ? bias : nullptr, Cp, row0, N, lane, wm, wn);
        __syncthreads();
        if (r < 2) {
            copy_B_async(Brel + (size_t)(r + 1) * (128 * 128), (r & 1) ? Bs1 : Bs0, tid);
            asm volatile("cp.async.commit_group;" ::: "memory");
        }
    }
}

// ---------------- cw1 GEMM with fused LN + exact GELU epilogue (512 threads) ----------------
__global__ __launch_bounds__(512) void mma_gemm1_lngelu_k(
    const float* __restrict__ A, const float* __restrict__ B,
    const float* __restrict__ bias, const float* __restrict__ lg,
    const float* __restrict__ lb, float* __restrict__ C, int N)
{
    extern __shared__ float sm[];
    float* As = sm;
    float* Bs = sm + 128 * SMA_STRIDE;

    const int tid  = threadIdx.x;
    const int row0 = blockIdx.x * 128;
    const int lane = tid & 31;
    const int wid  = tid >> 5;
    const int wm   = wid & 3;
    const int wn   = wid >> 2;

    stage_A(A, As, row0, N, tid);
    stage_B(B, Bs, tid);
    __syncthreads();
    float acc[2][4][4];
    acc_zero(acc);
    mma_compute_core(As, Bs, lane, wm, wn, acc, false);
    mma_ln_act_epilogue(acc, sm, bias, lg, lb, C, row0, N, lane, wm, wn, 1);
}

// ---------------- SIMT GEMM + fused LN+GELU (H3[128] @ cw2[128,64] -> H4) ----------------
__global__ __launch_bounds__(256) void gemm_lngelu_k(
    const float* __restrict__ A, const float* __restrict__ B,
    const float* __restrict__ bias, const float* __restrict__ lg,
    const float* __restrict__ lb, float* __restrict__ C, int N)
{
    const int K = 128, NC = 64;
    __shared__ float As[16][129];
    __shared__ float Bs[16][128];

    const int tid  = threadIdx.x;
    const int row0 = blockIdx.x * 128;
    const int tx   = tid & 15;
    const int ty   = tid >> 4;

    float acc[8][8];
    #pragma unroll
    for (int i = 0; i < 8; i++)
        #pragma unroll
        for (int j = 0; j < 8; j++) acc[i][j] = 0.f;

    for (int k0 = 0; k0 < K; k0 += 16) {
        #pragma unroll
        for (int p = 0; p < 2; p++) {
            int id = tid + p * 256;
            int r  = id >> 2;
            int kk = (id & 3) * 4;
            float4 v = make_float4(0.f, 0.f, 0.f, 0.f);
            int gr = row0 + r;
            if (gr < N) v = *(const float4*)&A[(size_t)gr * K + k0 + kk];
            As[kk + 0][r] = v.x; As[kk + 1][r] = v.y;
            As[kk + 2][r] = v.z; As[kk + 3][r] = v.w;
        }
        #pragma unroll
        for (int p = 0; p < 2; p++) {
            int id = tid + p * 256;
            int kk = id >> 5;
            int c  = (id & 31) * 4;
            float4 v = make_float4(0.f, 0.f, 0.f, 0.f);
            if (c + 3 < NC) v = *(const float4*)&B[(size_t)(k0 + kk) * NC + c];
            *(float4*)&Bs[kk][c] = v;
        }
        __syncthreads();
        #pragma unroll
        for (int kk = 0; kk < 16; kk++) {
            float a[8], b[8];
            #pragma unroll
            for (int i = 0; i < 8; i++) a[i] = As[kk][ty * 8 + i];
            #pragma unroll
            for (int j = 0; j < 8; j++) b[j] = Bs[kk][tx * 8 + j];
            #pragma unroll
            for (int i = 0; i < 8; i++)
                #pragma unroll
                for (int j = 0; j < 8; j++) acc[i][j] = fmaf(a[i], b[j], acc[i][j]);
        }
        __syncthreads();
    }

    const bool valid = (tx < 8);
    float bv[8], gv[8], lv[8];
    #pragma unroll
    for (int j = 0; j < 8; j++) {
        int c = tx * 8 + j;
        bv[j] = valid ? bias[c] : 0.f;
        gv[j] = valid ? lg[c]   : 0.f;
        lv[j] = valid ? lb[c]   : 0.f;
    }
    #pragma unroll
    for (int i = 0; i < 8; i++) {
        float s = 0.f, q = 0.f;
        #pragma unroll
        for (int j = 0; j < 8; j++) {
            float v = acc[i][j] + bv[j];
            acc[i][j] = v;
            if (valid) { s += v; q += v * v; }
        }
        s = hsum16(s); q = hsum16(q);
        float mean = s * (1.f / 64.f);
        float inv  = rsqrtf(q * (1.f / 64.f) - mean * mean + 1e-5f);
        int gr = row0 + ty * 8 + i;
        if (valid && gr < N) {
            #pragma unroll
            for (int j = 0; j < 8; j++) {
                float y = (acc[i][j] - mean) * inv * gv[j] + lv[j];
                y = 0.5f * y * (1.f + erff(y * 0.70710678118654752f));
                C[(size_t)gr * 64 + tx * 8 + j] = y;
            }
        }
    }
}

// ---------------- SIMT GEMM + fused log_softmax (H4[64] @ cw3[64,40] -> out) ----------------
__global__ __launch_bounds__(256) void gemm_logsoftmax_k(
    const float* __restrict__ A, const float* __restrict__ B,
    const float* __restrict__ bias, float* __restrict__ C, int N)
{
    const int K = 64, NC = OUTD;
    __shared__ float As[16][129];
    __shared__ float Bs[16][128];

    const int tid  = threadIdx.x;
    const int row0 = blockIdx.x * 128;
    const int tx   = tid & 15;
    const int ty   = tid >> 4;

    float acc[8][8];
    #pragma unroll
    for (int i = 0; i < 8; i++)
        #pragma unroll
        for (int j = 0; j < 8; j++) acc[i][j] = 0.f;

    for (int k0 = 0; k0 < K; k0 += 16) {
        #pragma unroll
        for (int p = 0; p < 2; p++) {
            int id = tid + p * 256;
            int r  = id >> 2;
            int kk = (id & 3) * 4;
            float4 v = make_float4(0.f, 0.f, 0.f, 0.f);
            int gr = row0 + r;
            if (gr < N) v = *(const float4*)&A[(size_t)gr * K + k0 + kk];
            As[kk + 0][r] = v.x; As[kk + 1][r] = v.y;
            As[kk + 2][r] = v.z; As[kk + 3][r] = v.w;
        }
        #pragma unroll
        for (int p = 0; p < 2; p++) {
            int id = tid + p * 256;
            int kk = id >> 5;
            int c  = (id & 31) * 4;
            float4 v = make_float4(0.f, 0.f, 0.f, 0.f);
            if (c + 3 < NC) v = *(const float4*)&B[(size_t)(k0 + kk) * NC + c];
            *(float4*)&Bs[kk][c] = v;
        }
        __syncthreads();
        #pragma unroll
        for (int kk = 0; kk < 16; kk++) {
            float a[8], b[8];
            #pragma unroll
            for (int i = 0; i < 8; i++) a[i] = As[kk][ty * 8 + i];
            #pragma unroll
            for (int j = 0; j < 8; j++) b[j] = Bs[kk][tx * 8 + j];
            #pragma unroll
            for (int i = 0; i < 8; i++)
                #pragma unroll
                for (int j = 0; j < 8; j++) acc[i][j] = fmaf(a[i], b[j], acc[i][j]);
        }
        __syncthreads();
    }

    const bool valid = (tx < 5);
    float bv[8];
    #pragma unroll
    for (int j = 0; j < 8; j++) {
        int c = tx * 8 + j;
        bv[j] = (c < NC) ? bias[c] : 0.f;
    }
    #pragma unroll
    for (int i = 0; i < 8; i++) {
        float m = -INFINITY;
        #pragma unroll
        for (int j = 0; j < 8; j++) {
            float v = acc[i][j] + bv[j];
            acc[i][j] = v;
            if (valid) m = fmaxf(m, v);
        }
        m = hmax16(m);
        float s = 0.f;
        if (valid) {
            #pragma unroll
            for (int j = 0; j < 8; j++) s += expf(acc[i][j] - m);
        }
        s = hsum16(s);
        float ls = m + logf(s);
        int gr = row0 + ty * 8 + i;
        if (valid && gr < N) {
            #pragma unroll
            for (int j = 0; j < 8; j++)
                C[(size_t)gr * NC + tx * 8 + j] = acc[i][j] - ls;
        }
    }
}

// ================= CSR build over (dst,type) buckets =================
__global__ void zero_deg_k(int* __restrict__ cur)
{
    int i = blockIdx.x * blockDim.x + threadIdx.x;
    if (i * 4 < NB) {
        int4 z = make_int4(0, 0, 0, 0);
        if (i * 4 + 3 < NB) ((int4*)cur)[i] = z;
        else for (int j = i * 4; j < NB; j++) cur[j] = 0;
    }
}
__global__ void hist_k(const int* __restrict__ ei, const int* __restrict__ et,
                       int* __restrict__ cur)
{
    int e4 = blockIdx.x * blockDim.x + threadIdx.x;
    if (e4 * 4 >= NE) return;
    int4 d = ((const int4*)(ei + NE))[e4];
    int4 t = ((const int4*)et)[e4];
    atomicAdd(&cur[d.x * NREL + t.x], 1);
    atomicAdd(&cur[d.y * NREL + t.y], 1);
    atomicAdd(&cur[d.z * NREL + t.z], 1);
    atomicAdd(&cur[d.w * NREL + t.w], 1);
}
__global__ __launch_bounds__(1024) void scan_k(int* __restrict__ cur, int* __restrict__ rowptr)
{
    __shared__ int part[1024];
    const int t = threadIdx.x;
    const int CH = (NB + 1023) / 1024;
    int base = t * CH;
    int s = 0;
    for (int i = 0; i < CH; i++) {
        int idx = base + i;
        if (idx < NB) s += cur[idx];
    }
    part[t] = s;
    __syncthreads();
    for (int off = 1; off < 1024; off <<= 1) {
        int v = 0;
        if (t >= off) v = part[t - off];
        __syncthreads();
        if (t >= off) part[t] += v;
        __syncthreads();
    }
    int run = (t == 0) ? 0 : part[t - 1];
    for (int i = 0; i < CH; i++) {
        int idx = base + i;
        if (idx < NB) {
            int d = cur[idx];
            rowptr[idx] = run;
            cur[idx] = run;
            run += d;
        }
    }
    if (t == 1023) rowptr[NB] = part[1023];
}
__global__ void fill_k(const int* __restrict__ ei, const int* __restrict__ et,
                       int* __restrict__ cur, unsigned* __restrict__ csr)
{
    int e4 = blockIdx.x * blockDim.x + threadIdx.x;
    if (e4 * 4 >= NE) return;
    int4 s = ((const int4*)ei)[e4];
    int4 d = ((const int4*)(ei + NE))[e4];
    int4 t = ((const int4*)et)[e4];
    csr[atomicAdd(&cur[d.x * NREL + t.x], 1)] = (unsigned)s.x;
    csr[atomicAdd(&cur[d.y * NREL + t.y], 1)] = (unsigned)s.y;
    csr[atomicAdd(&cur[d.z * NREL + t.z], 1)] = (unsigned)s.z;
    csr[atomicAdd(&cur[d.w * NREL + t.w], 1)] = (unsigned)s.w;
}

// ================= conv1 gather: segmented sum over H, fused LN+ReLU =================
__global__ __launch_bounds__(256) void gather_add_ln_k(
    const int* __restrict__ rowptr, const unsigned* __restrict__ csr,
    const float* __restrict__ A, const float* __restrict__ H,
    const float* __restrict__ g, const float* __restrict__ b,
    float* __restrict__ X1)
{
    int row = blockIdx.x * 8 + (threadIdx.x >> 5);
    if (row >= NN) return;
    int lane = threadIdx.x & 31;
    size_t base = (size_t)row * HD + lane * 4;

    float4 acc = *(const float4*)&A[base];
    #pragma unroll
    for (int t = 0; t < NREL; t++) {
        const float* Ht = H + (size_t)t * NN * HD + lane * 4;
        int e0 = rowptr[row * NREL + t], e1 = rowptr[row * NREL + t + 1];
        int e = e0;
        for (; e + 3 < e1; e += 4) {
            unsigned p0 = __ldg(&csr[e]),     p1 = __ldg(&csr[e + 1]);
            unsigned p2 = __ldg(&csr[e + 2]), p3 = __ldg(&csr[e + 3]);
            const float4 v0 = *(const float4*)&Ht[(size_t)p0 * HD];
            const float4 v1 = *(const float4*)&Ht[(size_t)p1 * HD];
            const float4 v2 = *(const float4*)&Ht[(size_t)p2 * HD];
            const float4 v3 = *(const float4*)&Ht[(size_t)p3 * HD];
            acc.x += (v0.x + v1.x) + (v2.x + v3.x);
            acc.y += (v0.y + v1.y) + (v2.y + v3.y);
            acc.z += (v0.z + v1.z) + (v2.z + v3.z);
            acc.w += (v0.w + v1.w) + (v2.w + v3.w);
        }
        for (; e < e1; e++) {
            unsigned p0 = __ldg(&csr[e]);
            const float4 v0 = *(const float4*)&Ht[(size_t)p0 * HD];
            acc.x += v0.x; acc.y += v0.y; acc.z += v0.z; acc.w += v0.w;
        }
    }

    float s  = acc.x + acc.y + acc.z + acc.w;
    float q  = acc.x * acc.x + acc.y * acc.y + acc.z * acc.z + acc.w * acc.w;
    s = wsum(s); q = wsum(q);
    float mean = s * (1.f / HD);
    float inv  = rsqrtf(q * (1.f / HD) - mean * mean + 1e-5f);
    int c = lane * 4;
    float4 y;
    y.x = fmaxf((acc.x - mean) * inv * g[c + 0] + b[c + 0], 0.f);
    y.y = fmaxf((acc.y - mean) * inv * g[c + 1] + b[c + 1], 0.f);
    y.z = fmaxf((acc.z - mean) * inv * g[c + 2] + b[c + 2], 0.f);
    y.w = fmaxf((acc.w - mean) * inv * g[c + 3] + b[c + 3], 0.f);
    *(float4*)&X1[base] = y;
}

// ================= conv2 gather: segmented per-relation max, fused LN+ReLU+res =================
__global__ __launch_bounds__(256) void gather_max_ln_k(
    const int* __restrict__ rowptr, const unsigned* __restrict__ csr,
    const float* __restrict__ A, const float* __restrict__ H,
    const float* __restrict__ X1, const float* __restrict__ g,
    const float* __restrict__ b, float* __restrict__ X2)
{
    int row = blockIdx.x * 8 + (threadIdx.x >> 5);
    if (row >= NN) return;
    int lane = threadIdx.x & 31;
    size_t base = (size_t)row * HD + lane * 4;

    float4 acc = *(const float4*)&A[base];
    #pragma unroll
    for (int t = 0; t < NREL; t++) {
        const float* Ht = H + (size_t)t * NN * HD + lane * 4;
        int e0 = rowptr[row * NREL + t], e1 = rowptr[row * NREL + t + 1];
        if (e0 == e1) continue;                   // empty segment -> contributes 0
        float4 m = make_float4(-INFINITY, -INFINITY, -INFINITY, -INFINITY);
        int e = e0;
        for (; e + 3 < e1; e += 4) {
            unsigned p0 = __ldg(&csr[e]),     p1 = __ldg(&csr[e + 1]);
            unsigned p2 = __ldg(&csr[e + 2]), p3 = __ldg(&csr[e + 3]);
            const float4 v0 = *(const float4*)&Ht[(size_t)p0 * HD];
            const float4 v1 = *(const float4*)&Ht[(size_t)p1 * HD];
            const float4 v2 = *(const float4*)&Ht[(size_t)p2 * HD];
            const float4 v3 = *(const float4*)&Ht[(size_t)p3 * HD];
            m.x = fmaxf(m.x, fmaxf(fmaxf(v0.x, v1.x), fmaxf(v2.x, v3.x)));
            m.y = fmaxf(m.y, fmaxf(fmaxf(v0.y, v1.y), fmaxf(v2.y, v3.y)));
            m.z = fmaxf(m.z, fmaxf(fmaxf(v0.z, v1.z), fmaxf(v2.z, v3.z)));
            m.w = fmaxf(m.w, fmaxf(fmaxf(v0.w, v1.w), fmaxf(v2.w, v3.w)));
        }
        for (; e < e1; e++) {
            unsigned p0 = __ldg(&csr[e]);
            const float4 v0 = *(const float4*)&Ht[(size_t)p0 * HD];
            m.x = fmaxf(m.x, v0.x); m.y = fmaxf(m.y, v0.y);
            m.z = fmaxf(m.z, v0.z); m.w = fmaxf(m.w, v0.w);
        }
        acc.x += m.x; acc.y += m.y; acc.z += m.z; acc.w += m.w;
    }

    float s = acc.x + acc.y + acc.z + acc.w;
    float q = acc.x * acc.x + acc.y * acc.y + acc.z * acc.z + acc.w * acc.w;
    s = wsum(s); q = wsum(q);
    float mean = s * (1.f / HD);
    float inv  = rsqrtf(q * (1.f / HD) - mean * mean + 1e-5f);
    float4 x1v = *(const float4*)&X1[base];
    int c = lane * 4;
    float4 y;
    y.x = fmaxf((acc.x - mean) * inv * g[c + 0] + b[c + 0], 0.f) + 0.2f * x1v.x;
    y.y = fmaxf((acc.y - mean) * inv * g[c + 1] + b[c + 1], 0.f) + 0.2f * x1v.y;
    y.z = fmaxf((acc.z - mean) * inv * g[c + 2] + b[c + 2], 0.f) + 0.2f * x1v.z;
    y.w = fmaxf((acc.w - mean) * inv * g[c + 3] + b[c + 3], 0.f) + 0.2f * x1v.w;
    *(float4*)&X2[base] = y;
}

// ---------------- host launcher ----------------
extern "C" void kernel_launch(void* const* d_in, const int* in_sizes, int n_in,
                              void* d_out, int out_size)
{
    const float* x       = (const float*)d_in[0];
    const int*   ei      = (const int*)  d_in[1];
    const int*   et      = (const int*)  d_in[2];
    const float* w1_rel  = (const float*)d_in[3];
    const float* w1_root = (const float*)d_in[4];
    const float* b1      = (const float*)d_in[5];
    const float* ln1_g   = (const float*)d_in[6];
    const float* ln1_b   = (const float*)d_in[7];
    const float* w2_rel  = (const float*)d_in[8];
    const float* w2_root = (const float*)d_in[9];
    const float* b2      = (const float*)d_in[10];
    const float* ln2_g   = (const float*)d_in[11];
    const float* ln2_b   = (const float*)d_in[12];
    const float* cw1     = (const float*)d_in[13];
    const float* cb1     = (const float*)d_in[14];
    const float* cln1_g  = (const float*)d_in[15];
    const float* cln1_b  = (const float*)d_in[16];
    const float* cw2     = (const float*)d_in[17];
    const float* cb2     = (const float*)d_in[18];
    const float* cln2_g  = (const float*)d_in[19];
    const float* cln2_b  = (const float*)d_in[20];
    const float* cw3     = (const float*)d_in[21];
    const float* cb3     = (const float*)d_in[22];
    float* out = (float*)d_out;

    float *H, *A, *X1, *X2, *H3, *H4;
    int *rowptr, *cur;
    unsigned* csr;
    cudaGetSymbolAddress((void**)&H,      g_H);
    cudaGetSymbolAddress((void**)&A,      g_A);
    cudaGetSymbolAddress((void**)&X1,     g_X1);
    cudaGetSymbolAddress((void**)&X2,     g_X2);
    cudaGetSymbolAddress((void**)&H3,     g_H3);
    cudaGetSymbolAddress((void**)&H4,     g_H4);
    cudaGetSymbolAddress((void**)&rowptr, g_rowptr);
    cudaGetSymbolAddress((void**)&cur,    g_cur);
    cudaGetSymbolAddress((void**)&csr,    g_csr);

    cudaFuncSetAttribute(mma_gemm4_k, cudaFuncAttributeMaxDynamicSharedMemorySize, MMA_SMEM4);
    cudaFuncSetAttribute(mma_gemm1_lngelu_k, cudaFuncAttributeMaxDynamicSharedMemorySize, MMA_SMEM1);

    const int gemmGrid = (NN + 127) / 128;   // 391
    const int rowGrid  = (NN + 7) / 8;       // 6250

    // ---- CSR build over (dst,type) ----
    zero_deg_k<<<(NB / 4 + 255) / 256, 256>>>(cur);
    hist_k<<<(NE / 4 + 255) / 256, 256>>>(ei, et, cur);
    scan_k<<<1, 1024>>>(cur, rowptr);
    fill_k<<<(NE / 4 + 255) / 256, 256>>>(ei, et, cur, csr);

    // ---- conv1 (aggr = add) ----
    mma_gemm4_k<<<gemmGrid, 512, MMA_SMEM4>>>(x, w1_root, w1_rel, b1, A, H, NN);
    gather_add_ln_k<<<rowGrid, 256>>>(rowptr, csr, A, H, ln1_g, ln1_b, X1);

    // ---- conv2 (aggr = per-relation max) ----
    mma_gemm4_k<<<gemmGrid, 512, MMA_SMEM4>>>(X1, w2_root, w2_rel, b2, A, H, NN);
    gather_max_ln_k<<<rowGrid, 256>>>(rowptr, csr, A, H, X1, ln2_g, ln2_b, X2);

    // ---- classifier (fused epilogues) ----
    mma_gemm1_lngelu_k<<<gemmGrid, 512, MMA_SMEM1>>>(X2, cw1, cb1, cln1_g, cln1_b, H3, NN);
    gemm_lngelu_k<<<gemmGrid, 256>>>(H3, cw2, cb2, cln2_g, cln2_b, H4, NN);
    gemm_logsoftmax_k<<<gemmGrid, 256>>>(H4, cw3, cb3, out, NN);
}

// round 14
// speedup vs baseline: 1.2370x; 1.2370x over previous
#include <cuda_runtime.h>
#include <cstdint>
#include <math.h>

#define NN   50000
#define NE   600000
#define HD   128
#define NREL 3
#define OUTD 40

// SMEM strides (floats) for conflict-free mma fragment loads:
#define SMA_STRIDE 132
#define SMB_STRIDE 136
#define MMA_SMEM4 ((128 * SMA_STRIDE + 2 * 128 * SMB_STRIDE) * 4)
#define MMA_SMEM1 ((128 * SMA_STRIDE + 128 * SMB_STRIDE) * 4)

// ---------------- scratch (device globals; no allocation) ----------------
static __device__ float g_H [(size_t)NREL * NN * HD];
static __device__ float g_A [(size_t)NN * HD];
static __device__ float g_X1[(size_t)NN * HD];
static __device__ float g_X2[(size_t)NN * HD];
static __device__ float g_H3[(size_t)NN * HD];
static __device__ float g_H4[(size_t)NN * 64];
static __device__ int      g_rowptr[NN + 1];
static __device__ int      g_cur[NN];
static __device__ unsigned g_csr[NE];     // (type<<16) | src

// ---------------- helpers ----------------
__device__ __forceinline__ float wsum(float v) {
    #pragma unroll
    for (int o = 16; o > 0; o >>= 1) v += __shfl_xor_sync(0xFFFFFFFFu, v, o);
    return v;
}
__device__ __forceinline__ float hsum16(float v) {
    #pragma unroll
    for (int o = 8; o > 0; o >>= 1) v += __shfl_xor_sync(0xFFFFFFFFu, v, o);
    return v;
}
__device__ __forceinline__ float hmax16(float v) {
    #pragma unroll
    for (int o = 8; o > 0; o >>= 1) v = fmaxf(v, __shfl_xor_sync(0xFFFFFFFFu, v, o));
    return v;
}
__device__ __forceinline__ float to_tf32(float x) {
    unsigned r;
    asm("cvt.rna.tf32.f32 %0, %1;" : "=r"(r) : "f"(x));
    return __uint_as_float(r);
}
__device__ __forceinline__ void mma_tf32(float* c, const unsigned* a, const unsigned* b) {
    asm volatile(
        "mma.sync.aligned.m16n8k8.row.col.f32.tf32.tf32.f32 "
        "{%0,%1,%2,%3}, {%4,%5,%6,%7}, {%8,%9}, {%0,%1,%2,%3};"
        : "+f"(c[0]), "+f"(c[1]), "+f"(c[2]), "+f"(c[3])
        : "r"(a[0]), "r"(a[1]), "r"(a[2]), "r"(a[3]), "r"(b[0]), "r"(b[1]));
}

// ================= MMA GEMM pieces (512 threads / 16 warps) =================
__device__ __forceinline__ void stage_A(const float* __restrict__ A, float* As,
                                        int row0, int N, int tid) {
    #pragma unroll
    for (int i = 0; i < 8; i++) {
        int idx = i * 512 + tid;
        int r = idx >> 5, c4 = (idx & 31) * 4;
        float4 v = make_float4(0.f, 0.f, 0.f, 0.f);
        if (row0 + r < N) v = *(const float4*)&A[(size_t)(row0 + r) * 128 + c4];
        v.x = to_tf32(v.x); v.y = to_tf32(v.y);
        v.z = to_tf32(v.z); v.w = to_tf32(v.w);
        *(float4*)&As[r * SMA_STRIDE + c4] = v;
    }
}
__device__ __forceinline__ void stage_B(const float* __restrict__ B, float* Bs, int tid) {
    #pragma unroll
    for (int i = 0; i < 8; i++) {
        int idx = i * 512 + tid;
        int k = idx >> 5, c4 = (idx & 31) * 4;
        float4 v = *(const float4*)&B[(size_t)k * 128 + c4];
        v.x = to_tf32(v.x); v.y = to_tf32(v.y);
        v.z = to_tf32(v.z); v.w = to_tf32(v.w);
        *(float4*)&Bs[k * SMB_STRIDE + c4] = v;
    }
}
__device__ __forceinline__ void copy_B_async(const float* __restrict__ B, float* Bs, int tid) {
    unsigned base = (unsigned)__cvta_generic_to_shared(Bs);
    #pragma unroll
    for (int i = 0; i < 8; i++) {
        int idx = i * 512 + tid;
        int k = idx >> 5, c4 = (idx & 31) * 4;
        asm volatile("cp.async.cg.shared.global [%0], [%1], 16;" ::
            "r"(base + (unsigned)((k * SMB_STRIDE + c4) * 4)),
            "l"(B + (size_t)k * 128 + c4) : "memory");
    }
}
__device__ __forceinline__ void acc_zero(float acc[2][4][4]) {
    #pragma unroll
    for (int mt = 0; mt < 2; mt++)
        #pragma unroll
        for (int nt = 0; nt < 4; nt++)
            #pragma unroll
            for (int q = 0; q < 4; q++) acc[mt][nt][q] = 0.f;
}
__device__ __forceinline__ void mma_compute_core(const float* As, const float* Bs,
                                                 int lane, int wm, int wn,
                                                 float acc[2][4][4], bool cvtB) {
    const float* Ab = As + (wm * 32 + (lane >> 2)) * SMA_STRIDE + (lane & 3);
    const float* Bb = Bs + (lane & 3) * SMB_STRIDE + wn * 32 + (lane >> 2);
    #pragma unroll
    for (int ks = 0; ks < 16; ks++) {
        unsigned a[2][4], b[4][2];
        #pragma unroll
        for (int mt = 0; mt < 2; mt++) {
            const float* p = Ab + mt * (16 * SMA_STRIDE) + ks * 8;
            a[mt][0] = __float_as_uint(p[0]);
            a[mt][1] = __float_as_uint(p[8 * SMA_STRIDE]);
            a[mt][2] = __float_as_uint(p[4]);
            a[mt][3] = __float_as_uint(p[8 * SMA_STRIDE + 4]);
        }
        #pragma unroll
        for (int nt = 0; nt < 4; nt++) {
            const float* p = Bb + ks * (8 * SMB_STRIDE) + nt * 8;
            if (cvtB) {
                b[nt][0] = __float_as_uint(to_tf32(p[0]));
                b[nt][1] = __float_as_uint(to_tf32(p[4 * SMB_STRIDE]));
            } else {
                b[nt][0] = __float_as_uint(p[0]);
                b[nt][1] = __float_as_uint(p[4 * SMB_STRIDE]);
            }
        }
        #pragma unroll
        for (int mt = 0; mt < 2; mt++)
            #pragma unroll
            for (int nt = 0; nt < 4; nt++)
                mma_tf32(acc[mt][nt], a[mt], b[nt]);
    }
}
__device__ __forceinline__ void mma_epilogue(float acc[2][4][4],
                                             const float* __restrict__ bias,
                                             float* __restrict__ C,
                                             int row0, int N, int lane, int wm, int wn) {
    #pragma unroll
    for (int nt = 0; nt < 4; nt++) {
        int c = wn * 32 + nt * 8 + (lane & 3) * 2;
        float b0 = bias ? bias[c] : 0.f;
        float b1 = bias ? bias[c + 1] : 0.f;
        #pragma unroll
        for (int mt = 0; mt < 2; mt++) {
            int r = row0 + wm * 32 + mt * 16 + (lane >> 2);
            float2 v0, v1;
            v0.x = acc[mt][nt][0] + b0; v0.y = acc[mt][nt][1] + b1;
            v1.x = acc[mt][nt][2] + b0; v1.y = acc[mt][nt][3] + b1;
            if (r < N)     *(float2*)&C[(size_t)r * 128 + c]       = v0;
            if (r + 8 < N) *(float2*)&C[(size_t)(r + 8) * 128 + c] = v1;
        }
    }
}
__device__ __forceinline__ void mma_ln_act_epilogue(
    float acc[2][4][4], float* sm,
    const float* __restrict__ bias, const float* __restrict__ lg,
    const float* __restrict__ lb, float* __restrict__ C,
    int row0, int N, int lane, int wm, int wn, int act)
{
    float bc[4][2];
    #pragma unroll
    for (int nt = 0; nt < 4; nt++) {
        int c = wn * 32 + nt * 8 + (lane & 3) * 2;
        bc[nt][0] = bias[c]; bc[nt][1] = bias[c + 1];
    }
    float psA[2], pqA[2], psB[2], pqB[2];
    #pragma unroll
    for (int mt = 0; mt < 2; mt++) {
        float sA = 0.f, qA = 0.f, sB = 0.f, qB = 0.f;
        #pragma unroll
        for (int nt = 0; nt < 4; nt++) {
            float v0 = acc[mt][nt][0] + bc[nt][0];
            float v1 = acc[mt][nt][1] + bc[nt][1];
            float v2 = acc[mt][nt][2] + bc[nt][0];
            float v3 = acc[mt][nt][3] + bc[nt][1];
            sA += v0 + v1; qA += v0 * v0 + v1 * v1;
            sB += v2 + v3; qB += v2 * v2 + v3 * v3;
        }
        #pragma unroll
        for (int o = 1; o < 4; o <<= 1) {
            sA += __shfl_xor_sync(0xFFFFFFFFu, sA, o);
            qA += __shfl_xor_sync(0xFFFFFFFFu, qA, o);
            sB += __shfl_xor_sync(0xFFFFFFFFu, sB, o);
            qB += __shfl_xor_sync(0xFFFFFFFFu, qB, o);
        }
        psA[mt] = sA; pqA[mt] = qA; psB[mt] = sB; pqB[mt] = qB;
    }
    __syncthreads();
    float* S1 = sm;
    float* S2 = sm + 512;
    if ((lane & 3) == 0) {
        #pragma unroll
        for (int mt = 0; mt < 2; mt++) {
            int rA = wm * 32 + mt * 16 + (lane >> 2);
            S1[rA * 4 + wn] = psA[mt];        S2[rA * 4 + wn] = pqA[mt];
            S1[(rA + 8) * 4 + wn] = psB[mt];  S2[(rA + 8) * 4 + wn] = pqB[mt];
        }
    }
    __syncthreads();
    #pragma unroll
    for (int mt = 0; mt < 2; mt++) {
        int rlA = wm * 32 + mt * 16 + (lane >> 2);
        int rlB = rlA + 8;
        float sA = S1[rlA * 4 + 0] + S1[rlA * 4 + 1] + S1[rlA * 4 + 2] + S1[rlA * 4 + 3];
        float qA = S2[rlA * 4 + 0] + S2[rlA * 4 + 1] + S2[rlA * 4 + 2] + S2[rlA * 4 + 3];
        float sB = S1[rlB * 4 + 0] + S1[rlB * 4 + 1] + S1[rlB * 4 + 2] + S1[rlB * 4 + 3];
        float qB = S2[rlB * 4 + 0] + S2[rlB * 4 + 1] + S2[rlB * 4 + 2] + S2[rlB * 4 + 3];
        float mA = sA * (1.f / HD), mB = sB * (1.f / HD);
        float iA = rsqrtf(qA * (1.f / HD) - mA * mA + 1e-5f);
        float iB = rsqrtf(qB * (1.f / HD) - mB * mB + 1e-5f);
        #pragma unroll
        for (int nt = 0; nt < 4; nt++) {
            int c = wn * 32 + nt * 8 + (lane & 3) * 2;
            float g0 = lg[c], g1 = lg[c + 1], l0 = lb[c], l1 = lb[c + 1];
            float v0 = (acc[mt][nt][0] + bc[nt][0] - mA) * iA * g0 + l0;
            float v1 = (acc[mt][nt][1] + bc[nt][1] - mA) * iA * g1 + l1;
            float v2 = (acc[mt][nt][2] + bc[nt][0] - mB) * iB * g0 + l0;
            float v3 = (acc[mt][nt][3] + bc[nt][1] - mB) * iB * g1 + l1;
            if (act == 0) {
                v0 = fmaxf(v0, 0.f); v1 = fmaxf(v1, 0.f);
                v2 = fmaxf(v2, 0.f); v3 = fmaxf(v3, 0.f);
            } else {
                v0 = 0.5f * v0 * (1.f + erff(v0 * 0.70710678118654752f));
                v1 = 0.5f * v1 * (1.f + erff(v1 * 0.70710678118654752f));
                v2 = 0.5f * v2 * (1.f + erff(v2 * 0.70710678118654752f));
                v3 = 0.5f * v3 * (1.f + erff(v3 * 0.70710678118654752f));
            }
            int r = row0 + wm * 32 + mt * 16 + (lane >> 2);
            if (r < N)     { float2 w = {v0, v1}; *(float2*)&C[(size_t)r * 128 + c] = w; }
            if (r + 8 < N) { float2 w = {v2, v3}; *(float2*)&C[(size_t)(r + 8) * 128 + c] = w; }
        }
    }
}

// ---------------- conv 4-in-1 GEMM (512 threads, cp.async double-buffered B) ----------------
__global__ __launch_bounds__(512) void mma_gemm4_k(
    const float* __restrict__ A, const float* __restrict__ Broot,
    const float* __restrict__ Brel, const float* __restrict__ bias,
    float* __restrict__ Croot, float* __restrict__ Crel, int N)
{
    extern __shared__ float sm[];
    float* As  = sm;
    float* Bs0 = sm + 128 * SMA_STRIDE;
    float* Bs1 = Bs0 + 128 * SMB_STRIDE;

    const int tid  = threadIdx.x;
    const int row0 = blockIdx.x * 128;
    const int lane = tid & 31;
    const int wid  = tid >> 5;
    const int wm   = wid & 3;
    const int wn   = wid >> 2;

    copy_B_async(Broot, Bs0, tid);
    asm volatile("cp.async.commit_group;" ::: "memory");
    copy_B_async(Brel, Bs1, tid);
    asm volatile("cp.async.commit_group;" ::: "memory");
    stage_A(A, As, row0, N, tid);

    float acc[2][4][4];
    #pragma unroll
    for (int r = 0; r < 4; r++) {
        if (r == 3) asm volatile("cp.async.wait_group 0;" ::: "memory");
        else        asm volatile("cp.async.wait_group 1;" ::: "memory");
        __syncthreads();
        const float* Bs = (r & 1) ? Bs1 : Bs0;
        acc_zero(acc);
        mma_compute_core(As, Bs, lane, wm, wn, acc, true);
        float* Cp = (r == 0) ? Croot : Crel + (size_t)(r - 1) * NN * HD;
        mma_epilogue(acc, (r == 0) ? bias : nullptr, Cp, row0, N, lane, wm, wn);
        __syncthreads();
        if (r < 2) {
            copy_B_async(Brel + (size_t)(r + 1) * (128 * 128), (r & 1) ? Bs1 : Bs0, tid);
            asm volatile("cp.async.commit_group;" ::: "memory");
        }
    }
}

// ---------------- cw1 GEMM with fused LN + exact GELU epilogue (512 threads) ----------------
__global__ __launch_bounds__(512) void mma_gemm1_lngelu_k(
    const float* __restrict__ A, const float* __restrict__ B,
    const float* __restrict__ bias, const float* __restrict__ lg,
    const float* __restrict__ lb, float* __restrict__ C, int N)
{
    extern __shared__ float sm[];
    float* As = sm;
    float* Bs = sm + 128 * SMA_STRIDE;

    const int tid  = threadIdx.x;
    const int row0 = blockIdx.x * 128;
    const int lane = tid & 31;
    const int wid  = tid >> 5;
    const int wm   = wid & 3;
    const int wn   = wid >> 2;

    stage_A(A, As, row0, N, tid);
    stage_B(B, Bs, tid);
    __syncthreads();
    float acc[2][4][4];
    acc_zero(acc);
    mma_compute_core(As, Bs, lane, wm, wn, acc, false);
    mma_ln_act_epilogue(acc, sm, bias, lg, lb, C, row0, N, lane, wm, wn, 1);
}

// ---------------- SIMT GEMM + fused LN+GELU (H3[128] @ cw2[128,64] -> H4) ----------------
__global__ __launch_bounds__(256) void gemm_lngelu_k(
    const float* __restrict__ A, const float* __restrict__ B,
    const float* __restrict__ bias, const float* __restrict__ lg,
    const float* __restrict__ lb, float* __restrict__ C, int N)
{
    const int K = 128, NC = 64;
    __shared__ float As[16][129];
    __shared__ float Bs[16][128];

    const int tid  = threadIdx.x;
    const int row0 = blockIdx.x * 128;
    const int tx   = tid & 15;
    const int ty   = tid >> 4;

    float acc[8][8];
    #pragma unroll
    for (int i = 0; i < 8; i++)
        #pragma unroll
        for (int j = 0; j < 8; j++) acc[i][j] = 0.f;

    for (int k0 = 0; k0 < K; k0 += 16) {
        #pragma unroll
        for (int p = 0; p < 2; p++) {
            int id = tid + p * 256;
            int r  = id >> 2;
            int kk = (id & 3) * 4;
            float4 v = make_float4(0.f, 0.f, 0.f, 0.f);
            int gr = row0 + r;
            if (gr < N) v = *(const float4*)&A[(size_t)gr * K + k0 + kk];
            As[kk + 0][r] = v.x; As[kk + 1][r] = v.y;
            As[kk + 2][r] = v.z; As[kk + 3][r] = v.w;
        }
        #pragma unroll
        for (int p = 0; p < 2; p++) {
            int id = tid + p * 256;
            int kk = id >> 5;
            int c  = (id & 31) * 4;
            float4 v = make_float4(0.f, 0.f, 0.f, 0.f);
            if (c + 3 < NC) v = *(const float4*)&B[(size_t)(k0 + kk) * NC + c];
            *(float4*)&Bs[kk][c] = v;
        }
        __syncthreads();
        #pragma unroll
        for (int kk = 0; kk < 16; kk++) {
            float a[8], b[8];
            #pragma unroll
            for (int i = 0; i < 8; i++) a[i] = As[kk][ty * 8 + i];
            #pragma unroll
            for (int j = 0; j < 8; j++) b[j] = Bs[kk][tx * 8 + j];
            #pragma unroll
            for (int i = 0; i < 8; i++)
                #pragma unroll
                for (int j = 0; j < 8; j++) acc[i][j] = fmaf(a[i], b[j], acc[i][j]);
        }
        __syncthreads();
    }

    const bool valid = (tx < 8);
    float bv[8], gv[8], lv[8];
    #pragma unroll
    for (int j = 0; j < 8; j++) {
        int c = tx * 8 + j;
        bv[j] = valid ? bias[c] : 0.f;
        gv[j] = valid ? lg[c]   : 0.f;
        lv[j] = valid ? lb[c]   : 0.f;
    }
    #pragma unroll
    for (int i = 0; i < 8; i++) {
        float s = 0.f, q = 0.f;
        #pragma unroll
        for (int j = 0; j < 8; j++) {
            float v = acc[i][j] + bv[j];
            acc[i][j] = v;
            if (valid) { s += v; q += v * v; }
        }
        s = hsum16(s); q = hsum16(q);
        float mean = s * (1.f / 64.f);
        float inv  = rsqrtf(q * (1.f / 64.f) - mean * mean + 1e-5f);
        int gr = row0 + ty * 8 + i;
        if (valid && gr < N) {
            #pragma unroll
            for (int j = 0; j < 8; j++) {
                float y = (acc[i][j] - mean) * inv * gv[j] + lv[j];
                y = 0.5f * y * (1.f + erff(y * 0.70710678118654752f));
                C[(size_t)gr * 64 + tx * 8 + j] = y;
            }
        }
    }
}

// ---------------- SIMT GEMM + fused log_softmax (H4[64] @ cw3[64,40] -> out) ----------------
__global__ __launch_bounds__(256) void gemm_logsoftmax_k(
    const float* __restrict__ A, const float* __restrict__ B,
    const float* __restrict__ bias, float* __restrict__ C, int N)
{
    const int K = 64, NC = OUTD;
    __shared__ float As[16][129];
    __shared__ float Bs[16][128];

    const int tid  = threadIdx.x;
    const int row0 = blockIdx.x * 128;
    const int tx   = tid & 15;
    const int ty   = tid >> 4;

    float acc[8][8];
    #pragma unroll
    for (int i = 0; i < 8; i++)
        #pragma unroll
        for (int j = 0; j < 8; j++) acc[i][j] = 0.f;

    for (int k0 = 0; k0 < K; k0 += 16) {
        #pragma unroll
        for (int p = 0; p < 2; p++) {
            int id = tid + p * 256;
            int r  = id >> 2;
            int kk = (id & 3) * 4;
            float4 v = make_float4(0.f, 0.f, 0.f, 0.f);
            int gr = row0 + r;
            if (gr < N) v = *(const float4*)&A[(size_t)gr * K + k0 + kk];
            As[kk + 0][r] = v.x; As[kk + 1][r] = v.y;
            As[kk + 2][r] = v.z; As[kk + 3][r] = v.w;
        }
        #pragma unroll
        for (int p = 0; p < 2; p++) {
            int id = tid + p * 256;
            int kk = id >> 5;
            int c  = (id & 31) * 4;
            float4 v = make_float4(0.f, 0.f, 0.f, 0.f);
            if (c + 3 < NC) v = *(const float4*)&B[(size_t)(k0 + kk) * NC + c];
            *(float4*)&Bs[kk][c] = v;
        }
        __syncthreads();
        #pragma unroll
        for (int kk = 0; kk < 16; kk++) {
            float a[8], b[8];
            #pragma unroll
            for (int i = 0; i < 8; i++) a[i] = As[kk][ty * 8 + i];
            #pragma unroll
            for (int j = 0; j < 8; j++) b[j] = Bs[kk][tx * 8 + j];
            #pragma unroll
            for (int i = 0; i < 8; i++)
                #pragma unroll
                for (int j = 0; j < 8; j++) acc[i][j] = fmaf(a[i], b[j], acc[i][j]);
        }
        __syncthreads();
    }

    const bool valid = (tx < 5);
    float bv[8];
    #pragma unroll
    for (int j = 0; j < 8; j++) {
        int c = tx * 8 + j;
        bv[j] = (c < NC) ? bias[c] : 0.f;
    }
    #pragma unroll
    for (int i = 0; i < 8; i++) {
        float m = -INFINITY;
        #pragma unroll
        for (int j = 0; j < 8; j++) {
            float v = acc[i][j] + bv[j];
            acc[i][j] = v;
            if (valid) m = fmaxf(m, v);
        }
        m = hmax16(m);
        float s = 0.f;
        if (valid) {
            #pragma unroll
            for (int j = 0; j < 8; j++) s += expf(acc[i][j] - m);
        }
        s = hsum16(s);
        float ls = m + logf(s);
        int gr = row0 + ty * 8 + i;
        if (valid && gr < N) {
            #pragma unroll
            for (int j = 0; j < 8; j++)
                C[(size_t)gr * NC + tx * 8 + j] = acc[i][j] - ls;
        }
    }
}

// ================= CSR build =================
__global__ void zero_deg_k(int* __restrict__ cur)
{
    int i = blockIdx.x * blockDim.x + threadIdx.x;
    if (i * 4 < NN) {
        int4 z = make_int4(0, 0, 0, 0);
        if (i * 4 + 3 < NN) ((int4*)cur)[i] = z;
        else for (int j = i * 4; j < NN; j++) cur[j] = 0;
    }
}
__global__ void hist_k(const int* __restrict__ ei, int* __restrict__ cur)
{
    int e4 = blockIdx.x * blockDim.x + threadIdx.x;
    if (e4 * 4 >= NE) return;
    int4 d = ((const int4*)(ei + NE))[e4];
    atomicAdd(&cur[d.x], 1);
    atomicAdd(&cur[d.y], 1);
    atomicAdd(&cur[d.z], 1);
    atomicAdd(&cur[d.w], 1);
}
__global__ __launch_bounds__(1024) void scan_k(int* __restrict__ cur, int* __restrict__ rowptr)
{
    __shared__ int part[1024];
    const int t = threadIdx.x;
    const int CH = (NN + 1023) / 1024;
    int base = t * CH;
    int s = 0;
    for (int i = 0; i < CH; i++) {
        int idx = base + i;
        if (idx < NN) s += cur[idx];
    }
    part[t] = s;
    __syncthreads();
    for (int off = 1; off < 1024; off <<= 1) {
        int v = 0;
        if (t >= off) v = part[t - off];
        __syncthreads();
        if (t >= off) part[t] += v;
        __syncthreads();
    }
    int run = (t == 0) ? 0 : part[t - 1];
    for (int i = 0; i < CH; i++) {
        int idx = base + i;
        if (idx < NN) {
            int d = cur[idx];
            rowptr[idx] = run;
            cur[idx] = run;
            run += d;
        }
    }
    if (t == 1023) rowptr[NN] = part[1023];
}
__global__ void fill_k(const int* __restrict__ ei, const int* __restrict__ et,
                       int* __restrict__ cur, unsigned* __restrict__ csr)
{
    int e4 = blockIdx.x * blockDim.x + threadIdx.x;
    if (e4 * 4 >= NE) return;
    int4 s = ((const int4*)ei)[e4];
    int4 d = ((const int4*)(ei + NE))[e4];
    int4 t = ((const int4*)et)[e4];
    csr[atomicAdd(&cur[d.x], 1)] = (unsigned)s.x | ((unsigned)t.x << 16);
    csr[atomicAdd(&cur[d.y], 1)] = (unsigned)s.y | ((unsigned)t.y << 16);
    csr[atomicAdd(&cur[d.z], 1)] = (unsigned)s.z | ((unsigned)t.z << 16);
    csr[atomicAdd(&cur[d.w], 1)] = (unsigned)s.w | ((unsigned)t.w << 16);
}

// ================= conv1 gather: sum over H, fused LN+ReLU =================
__global__ __launch_bounds__(256) void gather_add_ln_k(
    const int* __restrict__ rowptr, const unsigned* __restrict__ csr,
    const float* __restrict__ A, const float* __restrict__ H,
    const float* __restrict__ g, const float* __restrict__ b,
    float* __restrict__ X1)
{
    int row = blockIdx.x * 8 + (threadIdx.x >> 5);
    if (row >= NN) return;
    int lane = threadIdx.x & 31;
    size_t base = (size_t)row * HD + lane * 4;

    float4 acc = *(const float4*)&A[base];
    int e0 = rowptr[row], e1 = rowptr[row + 1];
    int e = e0;
    for (; e + 3 < e1; e += 4) {
        unsigned p0 = __ldg(&csr[e]),     p1 = __ldg(&csr[e + 1]);
        unsigned p2 = __ldg(&csr[e + 2]), p3 = __ldg(&csr[e + 3]);
        const float4 v0 = *(const float4*)&H[((size_t)(p0 >> 16) * NN + (p0 & 0xFFFFu)) * HD + lane * 4];
        const float4 v1 = *(const float4*)&H[((size_t)(p1 >> 16) * NN + (p1 & 0xFFFFu)) * HD + lane * 4];
        const float4 v2 = *(const float4*)&H[((size_t)(p2 >> 16) * NN + (p2 & 0xFFFFu)) * HD + lane * 4];
        const float4 v3 = *(const float4*)&H[((size_t)(p3 >> 16) * NN + (p3 & 0xFFFFu)) * HD + lane * 4];
        acc.x += (v0.x + v1.x) + (v2.x + v3.x);
        acc.y += (v0.y + v1.y) + (v2.y + v3.y);
        acc.z += (v0.z + v1.z) + (v2.z + v3.z);
        acc.w += (v0.w + v1.w) + (v2.w + v3.w);
    }
    for (; e < e1; e++) {
        unsigned p0 = __ldg(&csr[e]);
        const float4 v0 = *(const float4*)&H[((size_t)(p0 >> 16) * NN + (p0 & 0xFFFFu)) * HD + lane * 4];
        acc.x += v0.x; acc.y += v0.y; acc.z += v0.z; acc.w += v0.w;
    }

    float s  = acc.x + acc.y + acc.z + acc.w;
    float q  = acc.x * acc.x + acc.y * acc.y + acc.z * acc.z + acc.w * acc.w;
    s = wsum(s); q = wsum(q);
    float mean = s * (1.f / HD);
    float inv  = rsqrtf(q * (1.f / HD) - mean * mean + 1e-5f);
    int c = lane * 4;
    float4 y;
    y.x = fmaxf((acc.x - mean) * inv * g[c + 0] + b[c + 0], 0.f);
    y.y = fmaxf((acc.y - mean) * inv * g[c + 1] + b[c + 1], 0.f);
    y.z = fmaxf((acc.z - mean) * inv * g[c + 2] + b[c + 2], 0.f);
    y.w = fmaxf((acc.w - mean) * inv * g[c + 3] + b[c + 3], 0.f);
    *(float4*)&X1[base] = y;
}

// ================= conv2 gather: per-relation max, fused LN+ReLU+res =================
// interleaved CSR; x4 unroll for MLP=4 on the H-load stream; branchy merges
__device__ __forceinline__ void merge_max(float4* m0, float4* m1, float4* m2,
                                          int t, const float4 v) {
    float4* m = (t == 0) ? m0 : (t == 1) ? m1 : m2;
    m->x = fmaxf(m->x, v.x); m->y = fmaxf(m->y, v.y);
    m->z = fmaxf(m->z, v.z); m->w = fmaxf(m->w, v.w);
}
__global__ __launch_bounds__(256) void gather_max_ln_k(
    const int* __restrict__ rowptr, const unsigned* __restrict__ csr,
    const float* __restrict__ A, const float* __restrict__ H,
    const float* __restrict__ X1, const float* __restrict__ g,
    const float* __restrict__ b, float* __restrict__ X2)
{
    int row = blockIdx.x * 8 + (threadIdx.x >> 5);
    if (row >= NN) return;
    int lane = threadIdx.x & 31;
    size_t base = (size_t)row * HD + lane * 4;

    float4 acc = *(const float4*)&A[base];
    float4 m0 = make_float4(-INFINITY, -INFINITY, -INFINITY, -INFINITY);
    float4 m1 = m0, m2 = m0;

    int e0 = rowptr[row], e1 = rowptr[row + 1];
    int e = e0;
    for (; e + 3 < e1; e += 4) {
        unsigned p0 = __ldg(&csr[e]),     p1 = __ldg(&csr[e + 1]);
        unsigned p2 = __ldg(&csr[e + 2]), p3 = __ldg(&csr[e + 3]);
        const float4 v0 = *(const float4*)&H[((size_t)(p0 >> 16) * NN + (p0 & 0xFFFFu)) * HD + lane * 4];
        const float4 v1 = *(const float4*)&H[((size_t)(p1 >> 16) * NN + (p1 & 0xFFFFu)) * HD + lane * 4];
        const float4 v2 = *(const float4*)&H[((size_t)(p2 >> 16) * NN + (p2 & 0xFFFFu)) * HD + lane * 4];
        const float4 v3 = *(const float4*)&H[((size_t)(p3 >> 16) * NN + (p3 & 0xFFFFu)) * HD + lane * 4];
        merge_max(&m0, &m1, &m2, p0 >> 16, v0);
        merge_max(&m0, &m1, &m2, p1 >> 16, v1);
        merge_max(&m0, &m1, &m2, p2 >> 16, v2);
        merge_max(&m0, &m1, &m2, p3 >> 16, v3);
    }
    for (; e < e1; e++) {
        unsigned p = __ldg(&csr[e]);
        const float4 v = *(const float4*)&H[((size_t)(p >> 16) * NN + (p & 0xFFFFu)) * HD + lane * 4];
        merge_max(&m0, &m1, &m2, p >> 16, v);
    }
    acc.x += (m0.x > -INFINITY ? m0.x : 0.f) + (m1.x > -INFINITY ? m1.x : 0.f) + (m2.x > -INFINITY ? m2.x : 0.f);
    acc.y += (m0.y > -INFINITY ? m0.y : 0.f) + (m1.y > -INFINITY ? m1.y : 0.f) + (m2.y > -INFINITY ? m2.y : 0.f);
    acc.z += (m0.z > -INFINITY ? m0.z : 0.f) + (m1.z > -INFINITY ? m1.z : 0.f) + (m2.z > -INFINITY ? m2.z : 0.f);
    acc.w += (m0.w > -INFINITY ? m0.w : 0.f) + (m1.w > -INFINITY ? m1.w : 0.f) + (m2.w > -INFINITY ? m2.w : 0.f);

    float s = acc.x + acc.y + acc.z + acc.w;
    float q = acc.x * acc.x + acc.y * acc.y + acc.z * acc.z + acc.w * acc.w;
    s = wsum(s); q = wsum(q);
    float mean = s * (1.f / HD);
    float inv  = rsqrtf(q * (1.f / HD) - mean * mean + 1e-5f);
    float4 x1v = *(const float4*)&X1[base];
    int c = lane * 4;
    float4 y;
    y.x = fmaxf((acc.x - mean) * inv * g[c + 0] + b[c + 0], 0.f) + 0.2f * x1v.x;
    y.y = fmaxf((acc.y - mean) * inv * g[c + 1] + b[c + 1], 0.f) + 0.2f * x1v.y;
    y.z = fmaxf((acc.z - mean) * inv * g[c + 2] + b[c + 2], 0.f) + 0.2f * x1v.z;
    y.w = fmaxf((acc.w - mean) * inv * g[c + 3] + b[c + 3], 0.f) + 0.2f * x1v.w;
    *(float4*)&X2[base] = y;
}

// ---------------- host launcher ----------------
extern "C" void kernel_launch(void* const* d_in, const int* in_sizes, int n_in,
                              void* d_out, int out_size)
{
    const float* x       = (const float*)d_in[0];
    const int*   ei      = (const int*)  d_in[1];
    const int*   et      = (const int*)  d_in[2];
    const float* w1_rel  = (const float*)d_in[3];
    const float* w1_root = (const float*)d_in[4];
    const float* b1      = (const float*)d_in[5];
    const float* ln1_g   = (const float*)d_in[6];
    const float* ln1_b   = (const float*)d_in[7];
    const float* w2_rel  = (const float*)d_in[8];
    const float* w2_root = (const float*)d_in[9];
    const float* b2      = (const float*)d_in[10];
    const float* ln2_g   = (const float*)d_in[11];
    const float* ln2_b   = (const float*)d_in[12];
    const float* cw1     = (const float*)d_in[13];
    const float* cb1     = (const float*)d_in[14];
    const float* cln1_g  = (const float*)d_in[15];
    const float* cln1_b  = (const float*)d_in[16];
    const float* cw2     = (const float*)d_in[17];
    const float* cb2     = (const float*)d_in[18];
    const float* cln2_g  = (const float*)d_in[19];
    const float* cln2_b  = (const float*)d_in[20];
    const float* cw3     = (const float*)d_in[21];
    const float* cb3     = (const float*)d_in[22];
    float* out = (float*)d_out;

    float *H, *A, *X1, *X2, *H3, *H4;
    int *rowptr, *cur;
    unsigned* csr;
    cudaGetSymbolAddress((void**)&H,      g_H);
    cudaGetSymbolAddress((void**)&A,      g_A);
    cudaGetSymbolAddress((void**)&X1,     g_X1);
    cudaGetSymbolAddress((void**)&X2,     g_X2);
    cudaGetSymbolAddress((void**)&H3,     g_H3);
    cudaGetSymbolAddress((void**)&H4,     g_H4);
    cudaGetSymbolAddress((void**)&rowptr, g_rowptr);
    cudaGetSymbolAddress((void**)&cur,    g_cur);
    cudaGetSymbolAddress((void**)&csr,    g_csr);

    cudaFuncSetAttribute(mma_gemm4_k, cudaFuncAttributeMaxDynamicSharedMemorySize, MMA_SMEM4);
    cudaFuncSetAttribute(mma_gemm1_lngelu_k, cudaFuncAttributeMaxDynamicSharedMemorySize, MMA_SMEM1);

    const int gemmGrid = (NN + 127) / 128;   // 391
    const int rowGrid  = (NN + 7) / 8;       // 6250

    // ---- CSR build (by dst) ----
    zero_deg_k<<<(NN / 4 + 255) / 256, 256>>>(cur);
    hist_k<<<(NE / 4 + 255) / 256, 256>>>(ei, cur);
    scan_k<<<1, 1024>>>(cur, rowptr);
    fill_k<<<(NE / 4 + 255) / 256, 256>>>(ei, et, cur, csr);

    // ---- conv1 (aggr = add) ----
    mma_gemm4_k<<<gemmGrid, 512, MMA_SMEM4>>>(x, w1_root, w1_rel, b1, A, H, NN);
    gather_add_ln_k<<<rowGrid, 256>>>(rowptr, csr, A, H, ln1_g, ln1_b, X1);

    // ---- conv2 (aggr = per-relation max) ----
    mma_gemm4_k<<<gemmGrid, 512, MMA_SMEM4>>>(X1, w2_root, w2_rel, b2, A, H, NN);
    gather_max_ln_k<<<rowGrid, 256>>>(rowptr, csr, A, H, X1, ln2_g, ln2_b, X2);

    // ---- classifier (fused epilogues) ----
    mma_gemm1_lngelu_k<<<gemmGrid, 512, MMA_SMEM1>>>(X2, cw1, cb1, cln1_g, cln1_b, H3, NN);
    gemm_lngelu_k<<<gemmGrid, 256>>>(H3, cw2, cb2, cln2_g, cln2_b, H4, NN);
    gemm_logsoftmax_k<<<gemmGrid, 256>>>(H4, cw3, cb3, out, NN);
}

// round 15
// speedup vs baseline: 1.3118x; 1.0605x over previous
#include <cuda_runtime.h>
#include <cstdint>
#include <math.h>

#define NN   50000
#define NE   600000
#define HD   128
#define NREL 3
#define OUTD 40

// SMEM strides (floats) for conflict-free mma fragment loads:
#define SMA_STRIDE 132
#define SMB_STRIDE 136
#define MMA_SMEM4 ((128 * SMA_STRIDE + 2 * 128 * SMB_STRIDE) * 4)
#define MMA_SMEM1 ((128 * SMA_STRIDE + 128 * SMB_STRIDE) * 4)

// ---------------- scratch (device globals; no allocation) ----------------
static __device__ float g_H [(size_t)NREL * NN * HD];
static __device__ float g_A [(size_t)NN * HD];
static __device__ float g_X1[(size_t)NN * HD];
static __device__ float g_X2[(size_t)NN * HD];
static __device__ float g_H3[(size_t)NN * HD];
static __device__ float g_H4[(size_t)NN * 64];
static __device__ int      g_rowptr[NN + 1];
static __device__ int      g_cur[NN];
static __device__ unsigned g_csr[NE];     // (type<<16) | src

// ---------------- helpers ----------------
__device__ __forceinline__ float wsum(float v) {
    #pragma unroll
    for (int o = 16; o > 0; o >>= 1) v += __shfl_xor_sync(0xFFFFFFFFu, v, o);
    return v;
}
__device__ __forceinline__ float hsum16(float v) {
    #pragma unroll
    for (int o = 8; o > 0; o >>= 1) v += __shfl_xor_sync(0xFFFFFFFFu, v, o);
    return v;
}
__device__ __forceinline__ float hmax16(float v) {
    #pragma unroll
    for (int o = 8; o > 0; o >>= 1) v = fmaxf(v, __shfl_xor_sync(0xFFFFFFFFu, v, o));
    return v;
}
__device__ __forceinline__ float to_tf32(float x) {
    unsigned r;
    asm("cvt.rna.tf32.f32 %0, %1;" : "=r"(r) : "f"(x));
    return __uint_as_float(r);
}
__device__ __forceinline__ void mma_tf32(float* c, const unsigned* a, const unsigned* b) {
    asm volatile(
        "mma.sync.aligned.m16n8k8.row.col.f32.tf32.tf32.f32 "
        "{%0,%1,%2,%3}, {%4,%5,%6,%7}, {%8,%9}, {%0,%1,%2,%3};"
        : "+f"(c[0]), "+f"(c[1]), "+f"(c[2]), "+f"(c[3])
        : "r"(a[0]), "r"(a[1]), "r"(a[2]), "r"(a[3]), "r"(b[0]), "r"(b[1]));
}

// ================= MMA GEMM pieces (512 threads / 16 warps) =================
__device__ __forceinline__ void stage_A(const float* __restrict__ A, float* As,
                                        int row0, int N, int tid) {
    #pragma unroll
    for (int i = 0; i < 8; i++) {
        int idx = i * 512 + tid;
        int r = idx >> 5, c4 = (idx & 31) * 4;
        float4 v = make_float4(0.f, 0.f, 0.f, 0.f);
        if (row0 + r < N) v = *(const float4*)&A[(size_t)(row0 + r) * 128 + c4];
        v.x = to_tf32(v.x); v.y = to_tf32(v.y);
        v.z = to_tf32(v.z); v.w = to_tf32(v.w);
        *(float4*)&As[r * SMA_STRIDE + c4] = v;
    }
}
__device__ __forceinline__ void stage_B(const float* __restrict__ B, float* Bs, int tid) {
    #pragma unroll
    for (int i = 0; i < 8; i++) {
        int idx = i * 512 + tid;
        int k = idx >> 5, c4 = (idx & 31) * 4;
        float4 v = *(const float4*)&B[(size_t)k * 128 + c4];
        v.x = to_tf32(v.x); v.y = to_tf32(v.y);
        v.z = to_tf32(v.z); v.w = to_tf32(v.w);
        *(float4*)&Bs[k * SMB_STRIDE + c4] = v;
    }
}
__device__ __forceinline__ void copy_B_async(const float* __restrict__ B, float* Bs, int tid) {
    unsigned base = (unsigned)__cvta_generic_to_shared(Bs);
    #pragma unroll
    for (int i = 0; i < 8; i++) {
        int idx = i * 512 + tid;
        int k = idx >> 5, c4 = (idx & 31) * 4;
        asm volatile("cp.async.cg.shared.global [%0], [%1], 16;" ::
            "r"(base + (unsigned)((k * SMB_STRIDE + c4) * 4)),
            "l"(B + (size_t)k * 128 + c4) : "memory");
    }
}
__device__ __forceinline__ void acc_zero(float acc[2][4][4]) {
    #pragma unroll
    for (int mt = 0; mt < 2; mt++)
        #pragma unroll
        for (int nt = 0; nt < 4; nt++)
            #pragma unroll
            for (int q = 0; q < 4; q++) acc[mt][nt][q] = 0.f;
}
__device__ __forceinline__ void mma_compute_core(const float* As, const float* Bs,
                                                 int lane, int wm, int wn,
                                                 float acc[2][4][4], bool cvtB) {
    const float* Ab = As + (wm * 32 + (lane >> 2)) * SMA_STRIDE + (lane & 3);
    const float* Bb = Bs + (lane & 3) * SMB_STRIDE + wn * 32 + (lane >> 2);
    #pragma unroll
    for (int ks = 0; ks < 16; ks++) {
        unsigned a[2][4], b[4][2];
        #pragma unroll
        for (int mt = 0; mt < 2; mt++) {
            const float* p = Ab + mt * (16 * SMA_STRIDE) + ks * 8;
            a[mt][0] = __float_as_uint(p[0]);
            a[mt][1] = __float_as_uint(p[8 * SMA_STRIDE]);
            a[mt][2] = __float_as_uint(p[4]);
            a[mt][3] = __float_as_uint(p[8 * SMA_STRIDE + 4]);
        }
        #pragma unroll
        for (int nt = 0; nt < 4; nt++) {
            const float* p = Bb + ks * (8 * SMB_STRIDE) + nt * 8;
            if (cvtB) {
                b[nt][0] = __float_as_uint(to_tf32(p[0]));
                b[nt][1] = __float_as_uint(to_tf32(p[4 * SMB_STRIDE]));
            } else {
                b[nt][0] = __float_as_uint(p[0]);
                b[nt][1] = __float_as_uint(p[4 * SMB_STRIDE]);
            }
        }
        #pragma unroll
        for (int mt = 0; mt < 2; mt++)
            #pragma unroll
            for (int nt = 0; nt < 4; nt++)
                mma_tf32(acc[mt][nt], a[mt], b[nt]);
    }
}
__device__ __forceinline__ void mma_epilogue(float acc[2][4][4],
                                             const float* __restrict__ bias,
                                             float* __restrict__ C,
                                             int row0, int N, int lane, int wm, int wn) {
    #pragma unroll
    for (int nt = 0; nt < 4; nt++) {
        int c = wn * 32 + nt * 8 + (lane & 3) * 2;
        float b0 = bias ? bias[c] : 0.f;
        float b1 = bias ? bias[c + 1] : 0.f;
        #pragma unroll
        for (int mt = 0; mt < 2; mt++) {
            int r = row0 + wm * 32 + mt * 16 + (lane >> 2);
            float2 v0, v1;
            v0.x = acc[mt][nt][0] + b0; v0.y = acc[mt][nt][1] + b1;
            v1.x = acc[mt][nt][2] + b0; v1.y = acc[mt][nt][3] + b1;
            if (r < N)     *(float2*)&C[(size_t)r * 128 + c]       = v0;
            if (r + 8 < N) *(float2*)&C[(size_t)(r + 8) * 128 + c] = v1;
        }
    }
}
__device__ __forceinline__ void mma_ln_act_epilogue(
    float acc[2][4][4], float* sm,
    const float* __restrict__ bias, const float* __restrict__ lg,
    const float* __restrict__ lb, float* __restrict__ C,
    int row0, int N, int lane, int wm, int wn, int act)
{
    float bc[4][2];
    #pragma unroll
    for (int nt = 0; nt < 4; nt++) {
        int c = wn * 32 + nt * 8 + (lane & 3) * 2;
        bc[nt][0] = bias[c]; bc[nt][1] = bias[c + 1];
    }
    float psA[2], pqA[2], psB[2], pqB[2];
    #pragma unroll
    for (int mt = 0; mt < 2; mt++) {
        float sA = 0.f, qA = 0.f, sB = 0.f, qB = 0.f;
        #pragma unroll
        for (int nt = 0; nt < 4; nt++) {
            float v0 = acc[mt][nt][0] + bc[nt][0];
            float v1 = acc[mt][nt][1] + bc[nt][1];
            float v2 = acc[mt][nt][2] + bc[nt][0];
            float v3 = acc[mt][nt][3] + bc[nt][1];
            sA += v0 + v1; qA += v0 * v0 + v1 * v1;
            sB += v2 + v3; qB += v2 * v2 + v3 * v3;
        }
        #pragma unroll
        for (int o = 1; o < 4; o <<= 1) {
            sA += __shfl_xor_sync(0xFFFFFFFFu, sA, o);
            qA += __shfl_xor_sync(0xFFFFFFFFu, qA, o);
            sB += __shfl_xor_sync(0xFFFFFFFFu, sB, o);
            qB += __shfl_xor_sync(0xFFFFFFFFu, qB, o);
        }
        psA[mt] = sA; pqA[mt] = qA; psB[mt] = sB; pqB[mt] = qB;
    }
    __syncthreads();
    float* S1 = sm;
    float* S2 = sm + 512;
    if ((lane & 3) == 0) {
        #pragma unroll
        for (int mt = 0; mt < 2; mt++) {
            int rA = wm * 32 + mt * 16 + (lane >> 2);
            S1[rA * 4 + wn] = psA[mt];        S2[rA * 4 + wn] = pqA[mt];
            S1[(rA + 8) * 4 + wn] = psB[mt];  S2[(rA + 8) * 4 + wn] = pqB[mt];
        }
    }
    __syncthreads();
    #pragma unroll
    for (int mt = 0; mt < 2; mt++) {
        int rlA = wm * 32 + mt * 16 + (lane >> 2);
        int rlB = rlA + 8;
        float sA = S1[rlA * 4 + 0] + S1[rlA * 4 + 1] + S1[rlA * 4 + 2] + S1[rlA * 4 + 3];
        float qA = S2[rlA * 4 + 0] + S2[rlA * 4 + 1] + S2[rlA * 4 + 2] + S2[rlA * 4 + 3];
        float sB = S1[rlB * 4 + 0] + S1[rlB * 4 + 1] + S1[rlB * 4 + 2] + S1[rlB * 4 + 3];
        float qB = S2[rlB * 4 + 0] + S2[rlB * 4 + 1] + S2[rlB * 4 + 2] + S2[rlB * 4 + 3];
        float mA = sA * (1.f / HD), mB = sB * (1.f / HD);
        float iA = rsqrtf(qA * (1.f / HD) - mA * mA + 1e-5f);
        float iB = rsqrtf(qB * (1.f / HD) - mB * mB + 1e-5f);
        #pragma unroll
        for (int nt = 0; nt < 4; nt++) {
            int c = wn * 32 + nt * 8 + (lane & 3) * 2;
            float g0 = lg[c], g1 = lg[c + 1], l0 = lb[c], l1 = lb[c + 1];
            float v0 = (acc[mt][nt][0] + bc[nt][0] - mA) * iA * g0 + l0;
            float v1 = (acc[mt][nt][1] + bc[nt][1] - mA) * iA * g1 + l1;
            float v2 = (acc[mt][nt][2] + bc[nt][0] - mB) * iB * g0 + l0;
            float v3 = (acc[mt][nt][3] + bc[nt][1] - mB) * iB * g1 + l1;
            if (act == 0) {
                v0 = fmaxf(v0, 0.f); v1 = fmaxf(v1, 0.f);
                v2 = fmaxf(v2, 0.f); v3 = fmaxf(v3, 0.f);
            } else {
                v0 = 0.5f * v0 * (1.f + erff(v0 * 0.70710678118654752f));
                v1 = 0.5f * v1 * (1.f + erff(v1 * 0.70710678118654752f));
                v2 = 0.5f * v2 * (1.f + erff(v2 * 0.70710678118654752f));
                v3 = 0.5f * v3 * (1.f + erff(v3 * 0.70710678118654752f));
            }
            int r = row0 + wm * 32 + mt * 16 + (lane >> 2);
            if (r < N)     { float2 w = {v0, v1}; *(float2*)&C[(size_t)r * 128 + c] = w; }
            if (r + 8 < N) { float2 w = {v2, v3}; *(float2*)&C[(size_t)(r + 8) * 128 + c] = w; }
        }
    }
}

// ---------------- conv 4-in-1 GEMM (512 threads, cp.async double-buffered B) ----------------
__global__ __launch_bounds__(512) void mma_gemm4_k(
    const float* __restrict__ A, const float* __restrict__ Broot,
    const float* __restrict__ Brel, const float* __restrict__ bias,
    float* __restrict__ Croot, float* __restrict__ Crel, int N)
{
    extern __shared__ float sm[];
    float* As  = sm;
    float* Bs0 = sm + 128 * SMA_STRIDE;
    float* Bs1 = Bs0 + 128 * SMB_STRIDE;

    const int tid  = threadIdx.x;
    const int row0 = blockIdx.x * 128;
    const int lane = tid & 31;
    const int wid  = tid >> 5;
    const int wm   = wid & 3;
    const int wn   = wid >> 2;

    copy_B_async(Broot, Bs0, tid);
    asm volatile("cp.async.commit_group;" ::: "memory");
    copy_B_async(Brel, Bs1, tid);
    asm volatile("cp.async.commit_group;" ::: "memory");
    stage_A(A, As, row0, N, tid);

    float acc[2][4][4];
    #pragma unroll
    for (int r = 0; r < 4; r++) {
        if (r == 3) asm volatile("cp.async.wait_group 0;" ::: "memory");
        else        asm volatile("cp.async.wait_group 1;" ::: "memory");
        __syncthreads();
        const float* Bs = (r & 1) ? Bs1 : Bs0;
        acc_zero(acc);
        mma_compute_core(As, Bs, lane, wm, wn, acc, true);
        float* Cp = (r == 0) ? Croot : Crel + (size_t)(r - 1) * NN * HD;
        mma_epilogue(acc, (r == 0) ? bias : nullptr, Cp, row0, N, lane, wm, wn);
        __syncthreads();
        if (r < 2) {
            copy_B_async(Brel + (size_t)(r + 1) * (128 * 128), (r & 1) ? Bs1 : Bs0, tid);
            asm volatile("cp.async.commit_group;" ::: "memory");
        }
    }
}

// ---------------- cw1 GEMM with fused LN + exact GELU epilogue (512 threads) ----------------
__global__ __launch_bounds__(512) void mma_gemm1_lngelu_k(
    const float* __restrict__ A, const float* __restrict__ B,
    const float* __restrict__ bias, const float* __restrict__ lg,
    const float* __restrict__ lb, float* __restrict__ C, int N)
{
    extern __shared__ float sm[];
    float* As = sm;
    float* Bs = sm + 128 * SMA_STRIDE;

    const int tid  = threadIdx.x;
    const int row0 = blockIdx.x * 128;
    const int lane = tid & 31;
    const int wid  = tid >> 5;
    const int wm   = wid & 3;
    const int wn   = wid >> 2;

    stage_A(A, As, row0, N, tid);
    stage_B(B, Bs, tid);
    __syncthreads();
    float acc[2][4][4];
    acc_zero(acc);
    mma_compute_core(As, Bs, lane, wm, wn, acc, false);
    mma_ln_act_epilogue(acc, sm, bias, lg, lb, C, row0, N, lane, wm, wn, 1);
}

// ---------------- SIMT GEMM + fused LN+GELU (H3[128] @ cw2[128,64] -> H4) ----------------
__global__ __launch_bounds__(256) void gemm_lngelu_k(
    const float* __restrict__ A, const float* __restrict__ B,
    const float* __restrict__ bias, const float* __restrict__ lg,
    const float* __restrict__ lb, float* __restrict__ C, int N)
{
    const int K = 128, NC = 64;
    __shared__ float As[16][129];
    __shared__ float Bs[16][128];

    const int tid  = threadIdx.x;
    const int row0 = blockIdx.x * 128;
    const int tx   = tid & 15;
    const int ty   = tid >> 4;

    float acc[8][8];
    #pragma unroll
    for (int i = 0; i < 8; i++)
        #pragma unroll
        for (int j = 0; j < 8; j++) acc[i][j] = 0.f;

    for (int k0 = 0; k0 < K; k0 += 16) {
        #pragma unroll
        for (int p = 0; p < 2; p++) {
            int id = tid + p * 256;
            int r  = id >> 2;
            int kk = (id & 3) * 4;
            float4 v = make_float4(0.f, 0.f, 0.f, 0.f);
            int gr = row0 + r;
            if (gr < N) v = *(const float4*)&A[(size_t)gr * K + k0 + kk];
            As[kk + 0][r] = v.x; As[kk + 1][r] = v.y;
            As[kk + 2][r] = v.z; As[kk + 3][r] = v.w;
        }
        #pragma unroll
        for (int p = 0; p < 2; p++) {
            int id = tid + p * 256;
            int kk = id >> 5;
            int c  = (id & 31) * 4;
            float4 v = make_float4(0.f, 0.f, 0.f, 0.f);
            if (c + 3 < NC) v = *(const float4*)&B[(size_t)(k0 + kk) * NC + c];
            *(float4*)&Bs[kk][c] = v;
        }
        __syncthreads();
        #pragma unroll
        for (int kk = 0; kk < 16; kk++) {
            float a[8], b[8];
            #pragma unroll
            for (int i = 0; i < 8; i++) a[i] = As[kk][ty * 8 + i];
            #pragma unroll
            for (int j = 0; j < 8; j++) b[j] = Bs[kk][tx * 8 + j];
            #pragma unroll
            for (int i = 0; i < 8; i++)
                #pragma unroll
                for (int j = 0; j < 8; j++) acc[i][j] = fmaf(a[i], b[j], acc[i][j]);
        }
        __syncthreads();
    }

    const bool valid = (tx < 8);
    float bv[8], gv[8], lv[8];
    #pragma unroll
    for (int j = 0; j < 8; j++) {
        int c = tx * 8 + j;
        bv[j] = valid ? bias[c] : 0.f;
        gv[j] = valid ? lg[c]   : 0.f;
        lv[j] = valid ? lb[c]   : 0.f;
    }
    #pragma unroll
    for (int i = 0; i < 8; i++) {
        float s = 0.f, q = 0.f;
        #pragma unroll
        for (int j = 0; j < 8; j++) {
            float v = acc[i][j] + bv[j];
            acc[i][j] = v;
            if (valid) { s += v; q += v * v; }
        }
        s = hsum16(s); q = hsum16(q);
        float mean = s * (1.f / 64.f);
        float inv  = rsqrtf(q * (1.f / 64.f) - mean * mean + 1e-5f);
        int gr = row0 + ty * 8 + i;
        if (valid && gr < N) {
            #pragma unroll
            for (int j = 0; j < 8; j++) {
                float y = (acc[i][j] - mean) * inv * gv[j] + lv[j];
                y = 0.5f * y * (1.f + erff(y * 0.70710678118654752f));
                C[(size_t)gr * 64 + tx * 8 + j] = y;
            }
        }
    }
}

// ---------------- SIMT GEMM + fused log_softmax (H4[64] @ cw3[64,40] -> out) ----------------
__global__ __launch_bounds__(256) void gemm_logsoftmax_k(
    const float* __restrict__ A, const float* __restrict__ B,
    const float* __restrict__ bias, float* __restrict__ C, int N)
{
    const int K = 64, NC = OUTD;
    __shared__ float As[16][129];
    __shared__ float Bs[16][128];

    const int tid  = threadIdx.x;
    const int row0 = blockIdx.x * 128;
    const int tx   = tid & 15;
    const int ty   = tid >> 4;

    float acc[8][8];
    #pragma unroll
    for (int i = 0; i < 8; i++)
        #pragma unroll
        for (int j = 0; j < 8; j++) acc[i][j] = 0.f;

    for (int k0 = 0; k0 < K; k0 += 16) {
        #pragma unroll
        for (int p = 0; p < 2; p++) {
            int id = tid + p * 256;
            int r  = id >> 2;
            int kk = (id & 3) * 4;
            float4 v = make_float4(0.f, 0.f, 0.f, 0.f);
            int gr = row0 + r;
            if (gr < N) v = *(const float4*)&A[(size_t)gr * K + k0 + kk];
            As[kk + 0][r] = v.x; As[kk + 1][r] = v.y;
            As[kk + 2][r] = v.z; As[kk + 3][r] = v.w;
        }
        #pragma unroll
        for (int p = 0; p < 2; p++) {
            int id = tid + p * 256;
            int kk = id >> 5;
            int c  = (id & 31) * 4;
            float4 v = make_float4(0.f, 0.f, 0.f, 0.f);
            if (c + 3 < NC) v = *(const float4*)&B[(size_t)(k0 + kk) * NC + c];
            *(float4*)&Bs[kk][c] = v;
        }
        __syncthreads();
        #pragma unroll
        for (int kk = 0; kk < 16; kk++) {
            float a[8], b[8];
            #pragma unroll
            for (int i = 0; i < 8; i++) a[i] = As[kk][ty * 8 + i];
            #pragma unroll
            for (int j = 0; j < 8; j++) b[j] = Bs[kk][tx * 8 + j];
            #pragma unroll
            for (int i = 0; i < 8; i++)
                #pragma unroll
                for (int j = 0; j < 8; j++) acc[i][j] = fmaf(a[i], b[j], acc[i][j]);
        }
        __syncthreads();
    }

    const bool valid = (tx < 5);
    float bv[8];
    #pragma unroll
    for (int j = 0; j < 8; j++) {
        int c = tx * 8 + j;
        bv[j] = (c < NC) ? bias[c] : 0.f;
    }
    #pragma unroll
    for (int i = 0; i < 8; i++) {
        float m = -INFINITY;
        #pragma unroll
        for (int j = 0; j < 8; j++) {
            float v = acc[i][j] + bv[j];
            acc[i][j] = v;
            if (valid) m = fmaxf(m, v);
        }
        m = hmax16(m);
        float s = 0.f;
        if (valid) {
            #pragma unroll
            for (int j = 0; j < 8; j++) s += expf(acc[i][j] - m);
        }
        s = hsum16(s);
        float ls = m + logf(s);
        int gr = row0 + ty * 8 + i;
        if (valid && gr < N) {
            #pragma unroll
            for (int j = 0; j < 8; j++)
                C[(size_t)gr * NC + tx * 8 + j] = acc[i][j] - ls;
        }
    }
}

// ================= CSR build =================
__global__ void zero_deg_k(int* __restrict__ cur)
{
    int i = blockIdx.x * blockDim.x + threadIdx.x;
    if (i * 4 < NN) {
        int4 z = make_int4(0, 0, 0, 0);
        if (i * 4 + 3 < NN) ((int4*)cur)[i] = z;
        else for (int j = i * 4; j < NN; j++) cur[j] = 0;
    }
}
__global__ void hist_k(const int* __restrict__ ei, int* __restrict__ cur)
{
    int e4 = blockIdx.x * blockDim.x + threadIdx.x;
    if (e4 * 4 >= NE) return;
    int4 d = ((const int4*)(ei + NE))[e4];
    atomicAdd(&cur[d.x], 1);
    atomicAdd(&cur[d.y], 1);
    atomicAdd(&cur[d.z], 1);
    atomicAdd(&cur[d.w], 1);
}
__global__ __launch_bounds__(1024) void scan_k(int* __restrict__ cur, int* __restrict__ rowptr)
{
    __shared__ int part[1024];
    const int t = threadIdx.x;
    const int CH = (NN + 1023) / 1024;
    int base = t * CH;
    int s = 0;
    for (int i = 0; i < CH; i++) {
        int idx = base + i;
        if (idx < NN) s += cur[idx];
    }
    part[t] = s;
    __syncthreads();
    for (int off = 1; off < 1024; off <<= 1) {
        int v = 0;
        if (t >= off) v = part[t - off];
        __syncthreads();
        if (t >= off) part[t] += v;
        __syncthreads();
    }
    int run = (t == 0) ? 0 : part[t - 1];
    for (int i = 0; i < CH; i++) {
        int idx = base + i;
        if (idx < NN) {
            int d = cur[idx];
            rowptr[idx] = run;
            cur[idx] = run;
            run += d;
        }
    }
    if (t == 1023) rowptr[NN] = part[1023];
}
__global__ void fill_k(const int* __restrict__ ei, const int* __restrict__ et,
                       int* __restrict__ cur, unsigned* __restrict__ csr)
{
    int e4 = blockIdx.x * blockDim.x + threadIdx.x;
    if (e4 * 4 >= NE) return;
    int4 s = ((const int4*)ei)[e4];
    int4 d = ((const int4*)(ei + NE))[e4];
    int4 t = ((const int4*)et)[e4];
    csr[atomicAdd(&cur[d.x], 1)] = (unsigned)s.x | ((unsigned)t.x << 16);
    csr[atomicAdd(&cur[d.y], 1)] = (unsigned)s.y | ((unsigned)t.y << 16);
    csr[atomicAdd(&cur[d.z], 1)] = (unsigned)s.z | ((unsigned)t.z << 16);
    csr[atomicAdd(&cur[d.w], 1)] = (unsigned)s.w | ((unsigned)t.w << 16);
}

// ================= conv1 gather: sum over H, fused LN+ReLU =================
__global__ __launch_bounds__(256) void gather_add_ln_k(
    const int* __restrict__ rowptr, const unsigned* __restrict__ csr,
    const float* __restrict__ A, const float* __restrict__ H,
    const float* __restrict__ g, const float* __restrict__ b,
    float* __restrict__ X1)
{
    int row = blockIdx.x * 8 + (threadIdx.x >> 5);
    if (row >= NN) return;
    int lane = threadIdx.x & 31;
    size_t base = (size_t)row * HD + lane * 4;

    float4 acc = *(const float4*)&A[base];
    int e0 = rowptr[row], e1 = rowptr[row + 1];
    int e = e0;
    for (; e + 3 < e1; e += 4) {
        unsigned p0 = __ldg(&csr[e]),     p1 = __ldg(&csr[e + 1]);
        unsigned p2 = __ldg(&csr[e + 2]), p3 = __ldg(&csr[e + 3]);
        const float4 v0 = *(const float4*)&H[((size_t)(p0 >> 16) * NN + (p0 & 0xFFFFu)) * HD + lane * 4];
        const float4 v1 = *(const float4*)&H[((size_t)(p1 >> 16) * NN + (p1 & 0xFFFFu)) * HD + lane * 4];
        const float4 v2 = *(const float4*)&H[((size_t)(p2 >> 16) * NN + (p2 & 0xFFFFu)) * HD + lane * 4];
        const float4 v3 = *(const float4*)&H[((size_t)(p3 >> 16) * NN + (p3 & 0xFFFFu)) * HD + lane * 4];
        acc.x += (v0.x + v1.x) + (v2.x + v3.x);
        acc.y += (v0.y + v1.y) + (v2.y + v3.y);
        acc.z += (v0.z + v1.z) + (v2.z + v3.z);
        acc.w += (v0.w + v1.w) + (v2.w + v3.w);
    }
    for (; e < e1; e++) {
        unsigned p0 = __ldg(&csr[e]);
        const float4 v0 = *(const float4*)&H[((size_t)(p0 >> 16) * NN + (p0 & 0xFFFFu)) * HD + lane * 4];
        acc.x += v0.x; acc.y += v0.y; acc.z += v0.z; acc.w += v0.w;
    }

    float s  = acc.x + acc.y + acc.z + acc.w;
    float q  = acc.x * acc.x + acc.y * acc.y + acc.z * acc.z + acc.w * acc.w;
    s = wsum(s); q = wsum(q);
    float mean = s * (1.f / HD);
    float inv  = rsqrtf(q * (1.f / HD) - mean * mean + 1e-5f);
    int c = lane * 4;
    float4 y;
    y.x = fmaxf((acc.x - mean) * inv * g[c + 0] + b[c + 0], 0.f);
    y.y = fmaxf((acc.y - mean) * inv * g[c + 1] + b[c + 1], 0.f);
    y.z = fmaxf((acc.z - mean) * inv * g[c + 2] + b[c + 2], 0.f);
    y.w = fmaxf((acc.w - mean) * inv * g[c + 3] + b[c + 3], 0.f);
    *(float4*)&X1[base] = y;
}

// ================= conv2 gather: per-relation max, fused LN+ReLU+res =================
// interleaved CSR; x4 unroll; explicit if/else merges (register-resident, no address-of)
__global__ __launch_bounds__(256) void gather_max_ln_k(
    const int* __restrict__ rowptr, const unsigned* __restrict__ csr,
    const float* __restrict__ A, const float* __restrict__ H,
    const float* __restrict__ X1, const float* __restrict__ g,
    const float* __restrict__ b, float* __restrict__ X2)
{
    int row = blockIdx.x * 8 + (threadIdx.x >> 5);
    if (row >= NN) return;
    int lane = threadIdx.x & 31;
    size_t base = (size_t)row * HD + lane * 4;

    float4 acc = *(const float4*)&A[base];
    float4 m0 = make_float4(-INFINITY, -INFINITY, -INFINITY, -INFINITY);
    float4 m1 = m0, m2 = m0;

    int e0 = rowptr[row], e1 = rowptr[row + 1];
    int e = e0;
    for (; e + 3 < e1; e += 4) {
        unsigned p0 = __ldg(&csr[e]),     p1 = __ldg(&csr[e + 1]);
        unsigned p2 = __ldg(&csr[e + 2]), p3 = __ldg(&csr[e + 3]);
        int t0 = p0 >> 16, t1 = p1 >> 16, t2 = p2 >> 16, t3 = p3 >> 16;
        const float4 v0 = *(const float4*)&H[((size_t)t0 * NN + (p0 & 0xFFFFu)) * HD + lane * 4];
        const float4 v1 = *(const float4*)&H[((size_t)t1 * NN + (p1 & 0xFFFFu)) * HD + lane * 4];
        const float4 v2 = *(const float4*)&H[((size_t)t2 * NN + (p2 & 0xFFFFu)) * HD + lane * 4];
        const float4 v3 = *(const float4*)&H[((size_t)t3 * NN + (p3 & 0xFFFFu)) * HD + lane * 4];
        if (t0 == 0) { m0.x = fmaxf(m0.x, v0.x); m0.y = fmaxf(m0.y, v0.y); m0.z = fmaxf(m0.z, v0.z); m0.w = fmaxf(m0.w, v0.w); }
        else if (t0 == 1) { m1.x = fmaxf(m1.x, v0.x); m1.y = fmaxf(m1.y, v0.y); m1.z = fmaxf(m1.z, v0.z); m1.w = fmaxf(m1.w, v0.w); }
        else { m2.x = fmaxf(m2.x, v0.x); m2.y = fmaxf(m2.y, v0.y); m2.z = fmaxf(m2.z, v0.z); m2.w = fmaxf(m2.w, v0.w); }
        if (t1 == 0) { m0.x = fmaxf(m0.x, v1.x); m0.y = fmaxf(m0.y, v1.y); m0.z = fmaxf(m0.z, v1.z); m0.w = fmaxf(m0.w, v1.w); }
        else if (t1 == 1) { m1.x = fmaxf(m1.x, v1.x); m1.y = fmaxf(m1.y, v1.y); m1.z = fmaxf(m1.z, v1.z); m1.w = fmaxf(m1.w, v1.w); }
        else { m2.x = fmaxf(m2.x, v1.x); m2.y = fmaxf(m2.y, v1.y); m2.z = fmaxf(m2.z, v1.z); m2.w = fmaxf(m2.w, v1.w); }
        if (t2 == 0) { m0.x = fmaxf(m0.x, v2.x); m0.y = fmaxf(m0.y, v2.y); m0.z = fmaxf(m0.z, v2.z); m0.w = fmaxf(m0.w, v2.w); }
        else if (t2 == 1) { m1.x = fmaxf(m1.x, v2.x); m1.y = fmaxf(m1.y, v2.y); m1.z = fmaxf(m1.z, v2.z); m1.w = fmaxf(m1.w, v2.w); }
        else { m2.x = fmaxf(m2.x, v2.x); m2.y = fmaxf(m2.y, v2.y); m2.z = fmaxf(m2.z, v2.z); m2.w = fmaxf(m2.w, v2.w); }
        if (t3 == 0) { m0.x = fmaxf(m0.x, v3.x); m0.y = fmaxf(m0.y, v3.y); m0.z = fmaxf(m0.z, v3.z); m0.w = fmaxf(m0.w, v3.w); }
        else if (t3 == 1) { m1.x = fmaxf(m1.x, v3.x); m1.y = fmaxf(m1.y, v3.y); m1.z = fmaxf(m1.z, v3.z); m1.w = fmaxf(m1.w, v3.w); }
        else { m2.x = fmaxf(m2.x, v3.x); m2.y = fmaxf(m2.y, v3.y); m2.z = fmaxf(m2.z, v3.z); m2.w = fmaxf(m2.w, v3.w); }
    }
    for (; e < e1; e++) {
        unsigned p = __ldg(&csr[e]);
        int t = p >> 16;
        const float4 v = *(const float4*)&H[((size_t)t * NN + (p & 0xFFFFu)) * HD + lane * 4];
        if (t == 0) { m0.x = fmaxf(m0.x, v.x); m0.y = fmaxf(m0.y, v.y); m0.z = fmaxf(m0.z, v.z); m0.w = fmaxf(m0.w, v.w); }
        else if (t == 1) { m1.x = fmaxf(m1.x, v.x); m1.y = fmaxf(m1.y, v.y); m1.z = fmaxf(m1.z, v.z); m1.w = fmaxf(m1.w, v.w); }
        else { m2.x = fmaxf(m2.x, v.x); m2.y = fmaxf(m2.y, v.y); m2.z = fmaxf(m2.z, v.z); m2.w = fmaxf(m2.w, v.w); }
    }
    acc.x += (m0.x > -INFINITY ? m0.x : 0.f) + (m1.x > -INFINITY ? m1.x : 0.f) + (m2.x > -INFINITY ? m2.x : 0.f);
    acc.y += (m0.y > -INFINITY ? m0.y : 0.f) + (m1.y > -INFINITY ? m1.y : 0.f) + (m2.y > -INFINITY ? m2.y : 0.f);
    acc.z += (m0.z > -INFINITY ? m0.z : 0.f) + (m1.z > -INFINITY ? m1.z : 0.f) + (m2.z > -INFINITY ? m2.z : 0.f);
    acc.w += (m0.w > -INFINITY ? m0.w : 0.f) + (m1.w > -INFINITY ? m1.w : 0.f) + (m2.w > -INFINITY ? m2.w : 0.f);

    float s = acc.x + acc.y + acc.z + acc.w;
    float q = acc.x * acc.x + acc.y * acc.y + acc.z * acc.z + acc.w * acc.w;
    s = wsum(s); q = wsum(q);
    float mean = s * (1.f / HD);
    float inv  = rsqrtf(q * (1.f / HD) - mean * mean + 1e-5f);
    float4 x1v = *(const float4*)&X1[base];
    int c = lane * 4;
    float4 y;
    y.x = fmaxf((acc.x - mean) * inv * g[c + 0] + b[c + 0], 0.f) + 0.2f * x1v.x;
    y.y = fmaxf((acc.y - mean) * inv * g[c + 1] + b[c + 1], 0.f) + 0.2f * x1v.y;
    y.z = fmaxf((acc.z - mean) * inv * g[c + 2] + b[c + 2], 0.f) + 0.2f * x1v.z;
    y.w = fmaxf((acc.w - mean) * inv * g[c + 3] + b[c + 3], 0.f) + 0.2f * x1v.w;
    *(float4*)&X2[base] = y;
}

// ---------------- host launcher ----------------
extern "C" void kernel_launch(void* const* d_in, const int* in_sizes, int n_in,
                              void* d_out, int out_size)
{
    const float* x       = (const float*)d_in[0];
    const int*   ei      = (const int*)  d_in[1];
    const int*   et      = (const int*)  d_in[2];
    const float* w1_rel  = (const float*)d_in[3];
    const float* w1_root = (const float*)d_in[4];
    const float* b1      = (const float*)d_in[5];
    const float* ln1_g   = (const float*)d_in[6];
    const float* ln1_b   = (const float*)d_in[7];
    const float* w2_rel  = (const float*)d_in[8];
    const float* w2_root = (const float*)d_in[9];
    const float* b2      = (const float*)d_in[10];
    const float* ln2_g   = (const float*)d_in[11];
    const float* ln2_b   = (const float*)d_in[12];
    const float* cw1     = (const float*)d_in[13];
    const float* cb1     = (const float*)d_in[14];
    const float* cln1_g  = (const float*)d_in[15];
    const float* cln1_b  = (const float*)d_in[16];
    const float* cw2     = (const float*)d_in[17];
    const float* cb2     = (const float*)d_in[18];
    const float* cln2_g  = (const float*)d_in[19];
    const float* cln2_b  = (const float*)d_in[20];
    const float* cw3     = (const float*)d_in[21];
    const float* cb3     = (const float*)d_in[22];
    float* out = (float*)d_out;

    float *H, *A, *X1, *X2, *H3, *H4;
    int *rowptr, *cur;
    unsigned* csr;
    cudaGetSymbolAddress((void**)&H,      g_H);
    cudaGetSymbolAddress((void**)&A,      g_A);
    cudaGetSymbolAddress((void**)&X1,     g_X1);
    cudaGetSymbolAddress((void**)&X2,     g_X2);
    cudaGetSymbolAddress((void**)&H3,     g_H3);
    cudaGetSymbolAddress((void**)&H4,     g_H4);
    cudaGetSymbolAddress((void**)&rowptr, g_rowptr);
    cudaGetSymbolAddress((void**)&cur,    g_cur);
    cudaGetSymbolAddress((void**)&csr,    g_csr);

    cudaFuncSetAttribute(mma_gemm4_k, cudaFuncAttributeMaxDynamicSharedMemorySize, MMA_SMEM4);
    cudaFuncSetAttribute(mma_gemm1_lngelu_k, cudaFuncAttributeMaxDynamicSharedMemorySize, MMA_SMEM1);

    const int gemmGrid = (NN + 127) / 128;   // 391
    const int rowGrid  = (NN + 7) / 8;       // 6250

    // ---- CSR build (by dst) ----
    zero_deg_k<<<(NN / 4 + 255) / 256, 256>>>(cur);
    hist_k<<<(NE / 4 + 255) / 256, 256>>>(ei, cur);
    scan_k<<<1, 1024>>>(cur, rowptr);
    fill_k<<<(NE / 4 + 255) / 256, 256>>>(ei, et, cur, csr);

    // ---- conv1 (aggr = add) ----
    mma_gemm4_k<<<gemmGrid, 512, MMA_SMEM4>>>(x, w1_root, w1_rel, b1, A, H, NN);
    gather_add_ln_k<<<rowGrid, 256>>>(rowptr, csr, A, H, ln1_g, ln1_b, X1);

    // ---- conv2 (aggr = per-relation max) ----
    mma_gemm4_k<<<gemmGrid, 512, MMA_SMEM4>>>(X1, w2_root, w2_rel, b2, A, H, NN);
    gather_max_ln_k<<<rowGrid, 256>>>(rowptr, csr, A, H, X1, ln2_g, ln2_b, X2);

    // ---- classifier (fused epilogues) ----
    mma_gemm1_lngelu_k<<<gemmGrid, 512, MMA_SMEM1>>>(X2, cw1, cb1, cln1_g, cln1_b, H3, NN);
    gemm_lngelu_k<<<gemmGrid, 256>>>(H3, cw2, cb2, cln2_g, cln2_b, H4, NN);
    gemm_logsoftmax_k<<<gemmGrid, 256>>>(H4, cw3, cb3, out, NN);
}

// round 16
// speedup vs baseline: 1.3757x; 1.0487x over previous
#include <cuda_runtime.h>
#include <cuda_bf16.h>
#include <cstdint>
#include <math.h>

#define NN   50000
#define NE   600000
#define HD   128
#define NREL 3
#define OUTD 40

// SMEM strides (floats) for conflict-free mma fragment loads:
#define SMA_STRIDE 132
#define SMB_STRIDE 136
#define MMA_SMEM4 ((128 * SMA_STRIDE + 2 * 128 * SMB_STRIDE) * 4)
#define MMA_SMEM1 ((128 * SMA_STRIDE + 128 * SMB_STRIDE) * 4)

// ---------------- scratch (device globals; no allocation) ----------------
static __device__ __nv_bfloat16 g_H [(size_t)NREL * NN * HD];   // relation outputs, bf16
static __device__ float g_A [(size_t)NN * HD];                  // root output, fp32
static __device__ float g_X1[(size_t)NN * HD];
static __device__ float g_X2[(size_t)NN * HD];
static __device__ float g_H3[(size_t)NN * HD];
static __device__ float g_H4[(size_t)NN * 64];
static __device__ int      g_rowptr[NN + 1];
static __device__ int      g_cur[NN];
static __device__ unsigned g_csr[NE];     // (type<<16) | src

// ---------------- helpers ----------------
__device__ __forceinline__ float wsum(float v) {
    #pragma unroll
    for (int o = 16; o > 0; o >>= 1) v += __shfl_xor_sync(0xFFFFFFFFu, v, o);
    return v;
}
__device__ __forceinline__ float hsum16(float v) {
    #pragma unroll
    for (int o = 8; o > 0; o >>= 1) v += __shfl_xor_sync(0xFFFFFFFFu, v, o);
    return v;
}
__device__ __forceinline__ float hmax16(float v) {
    #pragma unroll
    for (int o = 8; o > 0; o >>= 1) v = fmaxf(v, __shfl_xor_sync(0xFFFFFFFFu, v, o));
    return v;
}
__device__ __forceinline__ float to_tf32(float x) {
    unsigned r;
    asm("cvt.rna.tf32.f32 %0, %1;" : "=r"(r) : "f"(x));
    return __uint_as_float(r);
}
__device__ __forceinline__ void mma_tf32(float* c, const unsigned* a, const unsigned* b) {
    asm volatile(
        "mma.sync.aligned.m16n8k8.row.col.f32.tf32.tf32.f32 "
        "{%0,%1,%2,%3}, {%4,%5,%6,%7}, {%8,%9}, {%0,%1,%2,%3};"
        : "+f"(c[0]), "+f"(c[1]), "+f"(c[2]), "+f"(c[3])
        : "r"(a[0]), "r"(a[1]), "r"(a[2]), "r"(a[3]), "r"(b[0]), "r"(b[1]));
}
// load 4 bf16 (8 bytes) -> float4
__device__ __forceinline__ float4 ld_bf4(const __nv_bfloat16* p) {
    uint2 u = *(const uint2*)p;
    float2 lo = __bfloat1622float2(*(const __nv_bfloat162*)&u.x);
    float2 hi = __bfloat1622float2(*(const __nv_bfloat162*)&u.y);
    return make_float4(lo.x, lo.y, hi.x, hi.y);
}

// ================= MMA GEMM pieces (512 threads / 16 warps) =================
__device__ __forceinline__ void stage_A(const float* __restrict__ A, float* As,
                                        int row0, int N, int tid) {
    #pragma unroll
    for (int i = 0; i < 8; i++) {
        int idx = i * 512 + tid;
        int r = idx >> 5, c4 = (idx & 31) * 4;
        float4 v = make_float4(0.f, 0.f, 0.f, 0.f);
        if (row0 + r < N) v = *(const float4*)&A[(size_t)(row0 + r) * 128 + c4];
        v.x = to_tf32(v.x); v.y = to_tf32(v.y);
        v.z = to_tf32(v.z); v.w = to_tf32(v.w);
        *(float4*)&As[r * SMA_STRIDE + c4] = v;
    }
}
__device__ __forceinline__ void stage_B(const float* __restrict__ B, float* Bs, int tid) {
    #pragma unroll
    for (int i = 0; i < 8; i++) {
        int idx = i * 512 + tid;
        int k = idx >> 5, c4 = (idx & 31) * 4;
        float4 v = *(const float4*)&B[(size_t)k * 128 + c4];
        v.x = to_tf32(v.x); v.y = to_tf32(v.y);
        v.z = to_tf32(v.z); v.w = to_tf32(v.w);
        *(float4*)&Bs[k * SMB_STRIDE + c4] = v;
    }
}
__device__ __forceinline__ void copy_B_async(const float* __restrict__ B, float* Bs, int tid) {
    unsigned base = (unsigned)__cvta_generic_to_shared(Bs);
    #pragma unroll
    for (int i = 0; i < 8; i++) {
        int idx = i * 512 + tid;
        int k = idx >> 5, c4 = (idx & 31) * 4;
        asm volatile("cp.async.cg.shared.global [%0], [%1], 16;" ::
            "r"(base + (unsigned)((k * SMB_STRIDE + c4) * 4)),
            "l"(B + (size_t)k * 128 + c4) : "memory");
    }
}
__device__ __forceinline__ void acc_zero(float acc[2][4][4]) {
    #pragma unroll
    for (int mt = 0; mt < 2; mt++)
        #pragma unroll
        for (int nt = 0; nt < 4; nt++)
            #pragma unroll
            for (int q = 0; q < 4; q++) acc[mt][nt][q] = 0.f;
}
__device__ __forceinline__ void mma_compute_core(const float* As, const float* Bs,
                                                 int lane, int wm, int wn,
                                                 float acc[2][4][4], bool cvtB) {
    const float* Ab = As + (wm * 32 + (lane >> 2)) * SMA_STRIDE + (lane & 3);
    const float* Bb = Bs + (lane & 3) * SMB_STRIDE + wn * 32 + (lane >> 2);
    #pragma unroll
    for (int ks = 0; ks < 16; ks++) {
        unsigned a[2][4], b[4][2];
        #pragma unroll
        for (int mt = 0; mt < 2; mt++) {
            const float* p = Ab + mt * (16 * SMA_STRIDE) + ks * 8;
            a[mt][0] = __float_as_uint(p[0]);
            a[mt][1] = __float_as_uint(p[8 * SMA_STRIDE]);
            a[mt][2] = __float_as_uint(p[4]);
            a[mt][3] = __float_as_uint(p[8 * SMA_STRIDE + 4]);
        }
        #pragma unroll
        for (int nt = 0; nt < 4; nt++) {
            const float* p = Bb + ks * (8 * SMB_STRIDE) + nt * 8;
            if (cvtB) {
                b[nt][0] = __float_as_uint(to_tf32(p[0]));
                b[nt][1] = __float_as_uint(to_tf32(p[4 * SMB_STRIDE]));
            } else {
                b[nt][0] = __float_as_uint(p[0]);
                b[nt][1] = __float_as_uint(p[4 * SMB_STRIDE]);
            }
        }
        #pragma unroll
        for (int mt = 0; mt < 2; mt++)
            #pragma unroll
            for (int nt = 0; nt < 4; nt++)
                mma_tf32(acc[mt][nt], a[mt], b[nt]);
    }
}
__device__ __forceinline__ void mma_epilogue_f32(float acc[2][4][4],
                                                 const float* __restrict__ bias,
                                                 float* __restrict__ C,
                                                 int row0, int N, int lane, int wm, int wn) {
    #pragma unroll
    for (int nt = 0; nt < 4; nt++) {
        int c = wn * 32 + nt * 8 + (lane & 3) * 2;
        float b0 = bias ? bias[c] : 0.f;
        float b1 = bias ? bias[c + 1] : 0.f;
        #pragma unroll
        for (int mt = 0; mt < 2; mt++) {
            int r = row0 + wm * 32 + mt * 16 + (lane >> 2);
            float2 v0, v1;
            v0.x = acc[mt][nt][0] + b0; v0.y = acc[mt][nt][1] + b1;
            v1.x = acc[mt][nt][2] + b0; v1.y = acc[mt][nt][3] + b1;
            if (r < N)     *(float2*)&C[(size_t)r * 128 + c]       = v0;
            if (r + 8 < N) *(float2*)&C[(size_t)(r + 8) * 128 + c] = v1;
        }
    }
}
__device__ __forceinline__ void mma_epilogue_bf16(float acc[2][4][4],
                                                  __nv_bfloat16* __restrict__ C,
                                                  int row0, int N, int lane, int wm, int wn) {
    #pragma unroll
    for (int nt = 0; nt < 4; nt++) {
        int c = wn * 32 + nt * 8 + (lane & 3) * 2;
        #pragma unroll
        for (int mt = 0; mt < 2; mt++) {
            int r = row0 + wm * 32 + mt * 16 + (lane >> 2);
            __nv_bfloat162 w0 = __floats2bfloat162_rn(acc[mt][nt][0], acc[mt][nt][1]);
            __nv_bfloat162 w1 = __floats2bfloat162_rn(acc[mt][nt][2], acc[mt][nt][3]);
            if (r < N)     *(__nv_bfloat162*)&C[(size_t)r * 128 + c]       = w0;
            if (r + 8 < N) *(__nv_bfloat162*)&C[(size_t)(r + 8) * 128 + c] = w1;
        }
    }
}
__device__ __forceinline__ void mma_ln_act_epilogue(
    float acc[2][4][4], float* sm,
    const float* __restrict__ bias, const float* __restrict__ lg,
    const float* __restrict__ lb, float* __restrict__ C,
    int row0, int N, int lane, int wm, int wn, int act)
{
    float bc[4][2];
    #pragma unroll
    for (int nt = 0; nt < 4; nt++) {
        int c = wn * 32 + nt * 8 + (lane & 3) * 2;
        bc[nt][0] = bias[c]; bc[nt][1] = bias[c + 1];
    }
    float psA[2], pqA[2], psB[2], pqB[2];
    #pragma unroll
    for (int mt = 0; mt < 2; mt++) {
        float sA = 0.f, qA = 0.f, sB = 0.f, qB = 0.f;
        #pragma unroll
        for (int nt = 0; nt < 4; nt++) {
            float v0 = acc[mt][nt][0] + bc[nt][0];
            float v1 = acc[mt][nt][1] + bc[nt][1];
            float v2 = acc[mt][nt][2] + bc[nt][0];
            float v3 = acc[mt][nt][3] + bc[nt][1];
            sA += v0 + v1; qA += v0 * v0 + v1 * v1;
            sB += v2 + v3; qB += v2 * v2 + v3 * v3;
        }
        #pragma unroll
        for (int o = 1; o < 4; o <<= 1) {
            sA += __shfl_xor_sync(0xFFFFFFFFu, sA, o);
            qA += __shfl_xor_sync(0xFFFFFFFFu, qA, o);
            sB += __shfl_xor_sync(0xFFFFFFFFu, sB, o);
            qB += __shfl_xor_sync(0xFFFFFFFFu, qB, o);
        }
        psA[mt] = sA; pqA[mt] = qA; psB[mt] = sB; pqB[mt] = qB;
    }
    __syncthreads();
    float* S1 = sm;
    float* S2 = sm + 512;
    if ((lane & 3) == 0) {
        #pragma unroll
        for (int mt = 0; mt < 2; mt++) {
            int rA = wm * 32 + mt * 16 + (lane >> 2);
            S1[rA * 4 + wn] = psA[mt];        S2[rA * 4 + wn] = pqA[mt];
            S1[(rA + 8) * 4 + wn] = psB[mt];  S2[(rA + 8) * 4 + wn] = pqB[mt];
        }
    }
    __syncthreads();
    #pragma unroll
    for (int mt = 0; mt < 2; mt++) {
        int rlA = wm * 32 + mt * 16 + (lane >> 2);
        int rlB = rlA + 8;
        float sA = S1[rlA * 4 + 0] + S1[rlA * 4 + 1] + S1[rlA * 4 + 2] + S1[rlA * 4 + 3];
        float qA = S2[rlA * 4 + 0] + S2[rlA * 4 + 1] + S2[rlA * 4 + 2] + S2[rlA * 4 + 3];
        float sB = S1[rlB * 4 + 0] + S1[rlB * 4 + 1] + S1[rlB * 4 + 2] + S1[rlB * 4 + 3];
        float qB = S2[rlB * 4 + 0] + S2[rlB * 4 + 1] + S2[rlB * 4 + 2] + S2[rlB * 4 + 3];
        float mA = sA * (1.f / HD), mB = sB * (1.f / HD);
        float iA = rsqrtf(qA * (1.f / HD) - mA * mA + 1e-5f);
        float iB = rsqrtf(qB * (1.f / HD) - mB * mB + 1e-5f);
        #pragma unroll
        for (int nt = 0; nt < 4; nt++) {
            int c = wn * 32 + nt * 8 + (lane & 3) * 2;
            float g0 = lg[c], g1 = lg[c + 1], l0 = lb[c], l1 = lb[c + 1];
            float v0 = (acc[mt][nt][0] + bc[nt][0] - mA) * iA * g0 + l0;
            float v1 = (acc[mt][nt][1] + bc[nt][1] - mA) * iA * g1 + l1;
            float v2 = (acc[mt][nt][2] + bc[nt][0] - mB) * iB * g0 + l0;
            float v3 = (acc[mt][nt][3] + bc[nt][1] - mB) * iB * g1 + l1;
            if (act == 0) {
                v0 = fmaxf(v0, 0.f); v1 = fmaxf(v1, 0.f);
                v2 = fmaxf(v2, 0.f); v3 = fmaxf(v3, 0.f);
            } else {
                v0 = 0.5f * v0 * (1.f + erff(v0 * 0.70710678118654752f));
                v1 = 0.5f * v1 * (1.f + erff(v1 * 0.70710678118654752f));
                v2 = 0.5f * v2 * (1.f + erff(v2 * 0.70710678118654752f));
                v3 = 0.5f * v3 * (1.f + erff(v3 * 0.70710678118654752f));
            }
            int r = row0 + wm * 32 + mt * 16 + (lane >> 2);
            if (r < N)     { float2 w = {v0, v1}; *(float2*)&C[(size_t)r * 128 + c] = w; }
            if (r + 8 < N) { float2 w = {v2, v3}; *(float2*)&C[(size_t)(r + 8) * 128 + c] = w; }
        }
    }
}

// ---------------- conv 4-in-1 GEMM (512 threads, cp.async double-buffered B) ----------------
// root -> fp32 A; relations -> bf16 H
__global__ __launch_bounds__(512) void mma_gemm4_k(
    const float* __restrict__ A, const float* __restrict__ Broot,
    const float* __restrict__ Brel, const float* __restrict__ bias,
    float* __restrict__ Croot, __nv_bfloat16* __restrict__ Crel, int N)
{
    extern __shared__ float sm[];
    float* As  = sm;
    float* Bs0 = sm + 128 * SMA_STRIDE;
    float* Bs1 = Bs0 + 128 * SMB_STRIDE;

    const int tid  = threadIdx.x;
    const int row0 = blockIdx.x * 128;
    const int lane = tid & 31;
    const int wid  = tid >> 5;
    const int wm   = wid & 3;
    const int wn   = wid >> 2;

    copy_B_async(Broot, Bs0, tid);
    asm volatile("cp.async.commit_group;" ::: "memory");
    copy_B_async(Brel, Bs1, tid);
    asm volatile("cp.async.commit_group;" ::: "memory");
    stage_A(A, As, row0, N, tid);

    float acc[2][4][4];
    #pragma unroll
    for (int r = 0; r < 4; r++) {
        if (r == 3) asm volatile("cp.async.wait_group 0;" ::: "memory");
        else        asm volatile("cp.async.wait_group 1;" ::: "memory");
        __syncthreads();
        const float* Bs = (r & 1) ? Bs1 : Bs0;
        acc_zero(acc);
        mma_compute_core(As, Bs, lane, wm, wn, acc, true);
        if (r == 0)
            mma_epilogue_f32(acc, bias, Croot, row0, N, lane, wm, wn);
        else
            mma_epilogue_bf16(acc, Crel + (size_t)(r - 1) * NN * HD, row0, N, lane, wm, wn);
        __syncthreads();
        if (r < 2) {
            copy_B_async(Brel + (size_t)(r + 1) * (128 * 128), (r & 1) ? Bs1 : Bs0, tid);
            asm volatile("cp.async.commit_group;" ::: "memory");
        }
    }
}

// ---------------- cw1 GEMM with fused LN + exact GELU epilogue (512 threads) ----------------
__global__ __launch_bounds__(512) void mma_gemm1_lngelu_k(
    const float* __restrict__ A, const float* __restrict__ B,
    const float* __restrict__ bias, const float* __restrict__ lg,
    const float* __restrict__ lb, float* __restrict__ C, int N)
{
    extern __shared__ float sm[];
    float* As = sm;
    float* Bs = sm + 128 * SMA_STRIDE;

    const int tid  = threadIdx.x;
    const int row0 = blockIdx.x * 128;
    const int lane = tid & 31;
    const int wid  = tid >> 5;
    const int wm   = wid & 3;
    const int wn   = wid >> 2;

    stage_A(A, As, row0, N, tid);
    stage_B(B, Bs, tid);
    __syncthreads();
    float acc[2][4][4];
    acc_zero(acc);
    mma_compute_core(As, Bs, lane, wm, wn, acc, false);
    mma_ln_act_epilogue(acc, sm, bias, lg, lb, C, row0, N, lane, wm, wn, 1);
}

// ---------------- SIMT GEMM + fused LN+GELU (H3[128] @ cw2[128,64] -> H4) ----------------
__global__ __launch_bounds__(256) void gemm_lngelu_k(
    const float* __restrict__ A, const float* __restrict__ B,
    const float* __restrict__ bias, const float* __restrict__ lg,
    const float* __restrict__ lb, float* __restrict__ C, int N)
{
    const int K = 128, NC = 64;
    __shared__ float As[16][129];
    __shared__ float Bs[16][128];

    const int tid  = threadIdx.x;
    const int row0 = blockIdx.x * 128;
    const int tx   = tid & 15;
    const int ty   = tid >> 4;

    float acc[8][8];
    #pragma unroll
    for (int i = 0; i < 8; i++)
        #pragma unroll
        for (int j = 0; j < 8; j++) acc[i][j] = 0.f;

    for (int k0 = 0; k0 < K; k0 += 16) {
        #pragma unroll
        for (int p = 0; p < 2; p++) {
            int id = tid + p * 256;
            int r  = id >> 2;
            int kk = (id & 3) * 4;
            float4 v = make_float4(0.f, 0.f, 0.f, 0.f);
            int gr = row0 + r;
            if (gr < N) v = *(const float4*)&A[(size_t)gr * K + k0 + kk];
            As[kk + 0][r] = v.x; As[kk + 1][r] = v.y;
            As[kk + 2][r] = v.z; As[kk + 3][r] = v.w;
        }
        #pragma unroll
        for (int p = 0; p < 2; p++) {
            int id = tid + p * 256;
            int kk = id >> 5;
            int c  = (id & 31) * 4;
            float4 v = make_float4(0.f, 0.f, 0.f, 0.f);
            if (c + 3 < NC) v = *(const float4*)&B[(size_t)(k0 + kk) * NC + c];
            *(float4*)&Bs[kk][c] = v;
        }
        __syncthreads();
        #pragma unroll
        for (int kk = 0; kk < 16; kk++) {
            float a[8], b[8];
            #pragma unroll
            for (int i = 0; i < 8; i++) a[i] = As[kk][ty * 8 + i];
            #pragma unroll
            for (int j = 0; j < 8; j++) b[j] = Bs[kk][tx * 8 + j];
            #pragma unroll
            for (int i = 0; i < 8; i++)
                #pragma unroll
                for (int j = 0; j < 8; j++) acc[i][j] = fmaf(a[i], b[j], acc[i][j]);
        }
        __syncthreads();
    }

    const bool valid = (tx < 8);
    float bv[8], gv[8], lv[8];
    #pragma unroll
    for (int j = 0; j < 8; j++) {
        int c = tx * 8 + j;
        bv[j] = valid ? bias[c] : 0.f;
        gv[j] = valid ? lg[c]   : 0.f;
        lv[j] = valid ? lb[c]   : 0.f;
    }
    #pragma unroll
    for (int i = 0; i < 8; i++) {
        float s = 0.f, q = 0.f;
        #pragma unroll
        for (int j = 0; j < 8; j++) {
            float v = acc[i][j] + bv[j];
            acc[i][j] = v;
            if (valid) { s += v; q += v * v; }
        }
        s = hsum16(s); q = hsum16(q);
        float mean = s * (1.f / 64.f);
        float inv  = rsqrtf(q * (1.f / 64.f) - mean * mean + 1e-5f);
        int gr = row0 + ty * 8 + i;
        if (valid && gr < N) {
            #pragma unroll
            for (int j = 0; j < 8; j++) {
                float y = (acc[i][j] - mean) * inv * gv[j] + lv[j];
                y = 0.5f * y * (1.f + erff(y * 0.70710678118654752f));
                C[(size_t)gr * 64 + tx * 8 + j] = y;
            }
        }
    }
}

// ---------------- SIMT GEMM + fused log_softmax (H4[64] @ cw3[64,40] -> out) ----------------
__global__ __launch_bounds__(256) void gemm_logsoftmax_k(
    const float* __restrict__ A, const float* __restrict__ B,
    const float* __restrict__ bias, float* __restrict__ C, int N)
{
    const int K = 64, NC = OUTD;
    __shared__ float As[16][129];
    __shared__ float Bs[16][128];

    const int tid  = threadIdx.x;
    const int row0 = blockIdx.x * 128;
    const int tx   = tid & 15;
    const int ty   = tid >> 4;

    float acc[8][8];
    #pragma unroll
    for (int i = 0; i < 8; i++)
        #pragma unroll
        for (int j = 0; j < 8; j++) acc[i][j] = 0.f;

    for (int k0 = 0; k0 < K; k0 += 16) {
        #pragma unroll
        for (int p = 0; p < 2; p++) {
            int id = tid + p * 256;
            int r  = id >> 2;
            int kk = (id & 3) * 4;
            float4 v = make_float4(0.f, 0.f, 0.f, 0.f);
            int gr = row0 + r;
            if (gr < N) v = *(const float4*)&A[(size_t)gr * K + k0 + kk];
            As[kk + 0][r] = v.x; As[kk + 1][r] = v.y;
            As[kk + 2][r] = v.z; As[kk + 3][r] = v.w;
        }
        #pragma unroll
        for (int p = 0; p < 2; p++) {
            int id = tid + p * 256;
            int kk = id >> 5;
            int c  = (id & 31) * 4;
            float4 v = make_float4(0.f, 0.f, 0.f, 0.f);
            if (c + 3 < NC) v = *(const float4*)&B[(size_t)(k0 + kk) * NC + c];
            *(float4*)&Bs[kk][c] = v;
        }
        __syncthreads();
        #pragma unroll
        for (int kk = 0; kk < 16; kk++) {
            float a[8], b[8];
            #pragma unroll
            for (int i = 0; i < 8; i++) a[i] = As[kk][ty * 8 + i];
            #pragma unroll
            for (int j = 0; j < 8; j++) b[j] = Bs[kk][tx * 8 + j];
            #pragma unroll
            for (int i = 0; i < 8; i++)
                #pragma unroll
                for (int j = 0; j < 8; j++) acc[i][j] = fmaf(a[i], b[j], acc[i][j]);
        }
        __syncthreads();
    }

    const bool valid = (tx < 5);
    float bv[8];
    #pragma unroll
    for (int j = 0; j < 8; j++) {
        int c = tx * 8 + j;
        bv[j] = (c < NC) ? bias[c] : 0.f;
    }
    #pragma unroll
    for (int i = 0; i < 8; i++) {
        float m = -INFINITY;
        #pragma unroll
        for (int j = 0; j < 8; j++) {
            float v = acc[i][j] + bv[j];
            acc[i][j] = v;
            if (valid) m = fmaxf(m, v);
        }
        m = hmax16(m);
        float s = 0.f;
        if (valid) {
            #pragma unroll
            for (int j = 0; j < 8; j++) s += expf(acc[i][j] - m);
        }
        s = hsum16(s);
        float ls = m + logf(s);
        int gr = row0 + ty * 8 + i;
        if (valid && gr < N) {
            #pragma unroll
            for (int j = 0; j < 8; j++)
                C[(size_t)gr * NC + tx * 8 + j] = acc[i][j] - ls;
        }
    }
}

// ================= CSR build =================
__global__ void zero_deg_k(int* __restrict__ cur)
{
    int i = blockIdx.x * blockDim.x + threadIdx.x;
    if (i * 4 < NN) {
        int4 z = make_int4(0, 0, 0, 0);
        if (i * 4 + 3 < NN) ((int4*)cur)[i] = z;
        else for (int j = i * 4; j < NN; j++) cur[j] = 0;
    }
}
__global__ void hist_k(const int* __restrict__ ei, int* __restrict__ cur)
{
    int e4 = blockIdx.x * blockDim.x + threadIdx.x;
    if (e4 * 4 >= NE) return;
    int4 d = ((const int4*)(ei + NE))[e4];
    atomicAdd(&cur[d.x], 1);
    atomicAdd(&cur[d.y], 1);
    atomicAdd(&cur[d.z], 1);
    atomicAdd(&cur[d.w], 1);
}
__global__ __launch_bounds__(1024) void scan_k(int* __restrict__ cur, int* __restrict__ rowptr)
{
    __shared__ int part[1024];
    const int t = threadIdx.x;
    const int CH = (NN + 1023) / 1024;
    int base = t * CH;
    int s = 0;
    for (int i = 0; i < CH; i++) {
        int idx = base + i;
        if (idx < NN) s += cur[idx];
    }
    part[t] = s;
    __syncthreads();
    for (int off = 1; off < 1024; off <<= 1) {
        int v = 0;
        if (t >= off) v = part[t - off];
        __syncthreads();
        if (t >= off) part[t] += v;
        __syncthreads();
    }
    int run = (t == 0) ? 0 : part[t - 1];
    for (int i = 0; i < CH; i++) {
        int idx = base + i;
        if (idx < NN) {
            int d = cur[idx];
            rowptr[idx] = run;
            cur[idx] = run;
            run += d;
        }
    }
    if (t == 1023) rowptr[NN] = part[1023];
}
__global__ void fill_k(const int* __restrict__ ei, const int* __restrict__ et,
                       int* __restrict__ cur, unsigned* __restrict__ csr)
{
    int e4 = blockIdx.x * blockDim.x + threadIdx.x;
    if (e4 * 4 >= NE) return;
    int4 s = ((const int4*)ei)[e4];
    int4 d = ((const int4*)(ei + NE))[e4];
    int4 t = ((const int4*)et)[e4];
    csr[atomicAdd(&cur[d.x], 1)] = (unsigned)s.x | ((unsigned)t.x << 16);
    csr[atomicAdd(&cur[d.y], 1)] = (unsigned)s.y | ((unsigned)t.y << 16);
    csr[atomicAdd(&cur[d.z], 1)] = (unsigned)s.z | ((unsigned)t.z << 16);
    csr[atomicAdd(&cur[d.w], 1)] = (unsigned)s.w | ((unsigned)t.w << 16);
}

// ================= conv1 gather: sum over bf16 H, fused LN+ReLU =================
__global__ __launch_bounds__(256) void gather_add_ln_k(
    const int* __restrict__ rowptr, const unsigned* __restrict__ csr,
    const float* __restrict__ A, const __nv_bfloat16* __restrict__ H,
    const float* __restrict__ g, const float* __restrict__ b,
    float* __restrict__ X1)
{
    int row = blockIdx.x * 8 + (threadIdx.x >> 5);
    if (row >= NN) return;
    int lane = threadIdx.x & 31;
    size_t base = (size_t)row * HD + lane * 4;

    float4 acc = *(const float4*)&A[base];
    int e0 = rowptr[row], e1 = rowptr[row + 1];
    int e = e0;
    for (; e + 3 < e1; e += 4) {
        unsigned p0 = __ldg(&csr[e]),     p1 = __ldg(&csr[e + 1]);
        unsigned p2 = __ldg(&csr[e + 2]), p3 = __ldg(&csr[e + 3]);
        const float4 v0 = ld_bf4(&H[((size_t)(p0 >> 16) * NN + (p0 & 0xFFFFu)) * HD + lane * 4]);
        const float4 v1 = ld_bf4(&H[((size_t)(p1 >> 16) * NN + (p1 & 0xFFFFu)) * HD + lane * 4]);
        const float4 v2 = ld_bf4(&H[((size_t)(p2 >> 16) * NN + (p2 & 0xFFFFu)) * HD + lane * 4]);
        const float4 v3 = ld_bf4(&H[((size_t)(p3 >> 16) * NN + (p3 & 0xFFFFu)) * HD + lane * 4]);
        acc.x += (v0.x + v1.x) + (v2.x + v3.x);
        acc.y += (v0.y + v1.y) + (v2.y + v3.y);
        acc.z += (v0.z + v1.z) + (v2.z + v3.z);
        acc.w += (v0.w + v1.w) + (v2.w + v3.w);
    }
    for (; e < e1; e++) {
        unsigned p0 = __ldg(&csr[e]);
        const float4 v0 = ld_bf4(&H[((size_t)(p0 >> 16) * NN + (p0 & 0xFFFFu)) * HD + lane * 4]);
        acc.x += v0.x; acc.y += v0.y; acc.z += v0.z; acc.w += v0.w;
    }

    float s  = acc.x + acc.y + acc.z + acc.w;
    float q  = acc.x * acc.x + acc.y * acc.y + acc.z * acc.z + acc.w * acc.w;
    s = wsum(s); q = wsum(q);
    float mean = s * (1.f / HD);
    float inv  = rsqrtf(q * (1.f / HD) - mean * mean + 1e-5f);
    int c = lane * 4;
    float4 y;
    y.x = fmaxf((acc.x - mean) * inv * g[c + 0] + b[c + 0], 0.f);
    y.y = fmaxf((acc.y - mean) * inv * g[c + 1] + b[c + 1], 0.f);
    y.z = fmaxf((acc.z - mean) * inv * g[c + 2] + b[c + 2], 0.f);
    y.w = fmaxf((acc.w - mean) * inv * g[c + 3] + b[c + 3], 0.f);
    *(float4*)&X1[base] = y;
}

// ================= conv2 gather: per-relation max over bf16 H, fused LN+ReLU+res =================
__global__ __launch_bounds__(256) void gather_max_ln_k(
    const int* __restrict__ rowptr, const unsigned* __restrict__ csr,
    const float* __restrict__ A, const __nv_bfloat16* __restrict__ H,
    const float* __restrict__ X1, const float* __restrict__ g,
    const float* __restrict__ b, float* __restrict__ X2)
{
    int row = blockIdx.x * 8 + (threadIdx.x >> 5);
    if (row >= NN) return;
    int lane = threadIdx.x & 31;
    size_t base = (size_t)row * HD + lane * 4;

    float4 acc = *(const float4*)&A[base];
    float4 m0 = make_float4(-INFINITY, -INFINITY, -INFINITY, -INFINITY);
    float4 m1 = m0, m2 = m0;

    int e0 = rowptr[row], e1 = rowptr[row + 1];
    int e = e0;
    for (; e + 1 < e1; e += 2) {
        unsigned p0 = __ldg(&csr[e]), p1 = __ldg(&csr[e + 1]);
        int t0 = p0 >> 16, t1 = p1 >> 16;
        const float4 v0 = ld_bf4(&H[((size_t)t0 * NN + (p0 & 0xFFFFu)) * HD + lane * 4]);
        const float4 v1 = ld_bf4(&H[((size_t)t1 * NN + (p1 & 0xFFFFu)) * HD + lane * 4]);
        if (t0 == 0) { m0.x = fmaxf(m0.x, v0.x); m0.y = fmaxf(m0.y, v0.y); m0.z = fmaxf(m0.z, v0.z); m0.w = fmaxf(m0.w, v0.w); }
        else if (t0 == 1) { m1.x = fmaxf(m1.x, v0.x); m1.y = fmaxf(m1.y, v0.y); m1.z = fmaxf(m1.z, v0.z); m1.w = fmaxf(m1.w, v0.w); }
        else { m2.x = fmaxf(m2.x, v0.x); m2.y = fmaxf(m2.y, v0.y); m2.z = fmaxf(m2.z, v0.z); m2.w = fmaxf(m2.w, v0.w); }
        if (t1 == 0) { m0.x = fmaxf(m0.x, v1.x); m0.y = fmaxf(m0.y, v1.y); m0.z = fmaxf(m0.z, v1.z); m0.w = fmaxf(m0.w, v1.w); }
        else if (t1 == 1) { m1.x = fmaxf(m1.x, v1.x); m1.y = fmaxf(m1.y, v1.y); m1.z = fmaxf(m1.z, v1.z); m1.w = fmaxf(m1.w, v1.w); }
        else { m2.x = fmaxf(m2.x, v1.x); m2.y = fmaxf(m2.y, v1.y); m2.z = fmaxf(m2.z, v1.z); m2.w = fmaxf(m2.w, v1.w); }
    }
    if (e < e1) {
        unsigned p = __ldg(&csr[e]);
        int t = p >> 16;
        const float4 v = ld_bf4(&H[((size_t)t * NN + (p & 0xFFFFu)) * HD + lane * 4]);
        if (t == 0) { m0.x = fmaxf(m0.x, v.x); m0.y = fmaxf(m0.y, v.y); m0.z = fmaxf(m0.z, v.z); m0.w = fmaxf(m0.w, v.w); }
        else if (t == 1) { m1.x = fmaxf(m1.x, v.x); m1.y = fmaxf(m1.y, v.y); m1.z = fmaxf(m1.z, v.z); m1.w = fmaxf(m1.w, v.w); }
        else { m2.x = fmaxf(m2.x, v.x); m2.y = fmaxf(m2.y, v.y); m2.z = fmaxf(m2.z, v.z); m2.w = fmaxf(m2.w, v.w); }
    }
    acc.x += (m0.x > -INFINITY ? m0.x : 0.f) + (m1.x > -INFINITY ? m1.x : 0.f) + (m2.x > -INFINITY ? m2.x : 0.f);
    acc.y += (m0.y > -INFINITY ? m0.y : 0.f) + (m1.y > -INFINITY ? m1.y : 0.f) + (m2.y > -INFINITY ? m2.y : 0.f);
    acc.z += (m0.z > -INFINITY ? m0.z : 0.f) + (m1.z > -INFINITY ? m1.z : 0.f) + (m2.z > -INFINITY ? m2.z : 0.f);
    acc.w += (m0.w > -INFINITY ? m0.w : 0.f) + (m1.w > -INFINITY ? m1.w : 0.f) + (m2.w > -INFINITY ? m2.w : 0.f);

    float s = acc.x + acc.y + acc.z + acc.w;
    float q = acc.x * acc.x + acc.y * acc.y + acc.z * acc.z + acc.w * acc.w;
    s = wsum(s); q = wsum(q);
    float mean = s * (1.f / HD);
    float inv  = rsqrtf(q * (1.f / HD) - mean * mean + 1e-5f);
    float4 x1v = *(const float4*)&X1[base];
    int c = lane * 4;
    float4 y;
    y.x = fmaxf((acc.x - mean) * inv * g[c + 0] + b[c + 0], 0.f) + 0.2f * x1v.x;
    y.y = fmaxf((acc.y - mean) * inv * g[c + 1] + b[c + 1], 0.f) + 0.2f * x1v.y;
    y.z = fmaxf((acc.z - mean) * inv * g[c + 2] + b[c + 2], 0.f) + 0.2f * x1v.z;
    y.w = fmaxf((acc.w - mean) * inv * g[c + 3] + b[c + 3], 0.f) + 0.2f * x1v.w;
    *(float4*)&X2[base] = y;
}

// ---------------- host launcher ----------------
extern "C" void kernel_launch(void* const* d_in, const int* in_sizes, int n_in,
                              void* d_out, int out_size)
{
    const float* x       = (const float*)d_in[0];
    const int*   ei      = (const int*)  d_in[1];
    const int*   et      = (const int*)  d_in[2];
    const float* w1_rel  = (const float*)d_in[3];
    const float* w1_root = (const float*)d_in[4];
    const float* b1      = (const float*)d_in[5];
    const float* ln1_g   = (const float*)d_in[6];
    const float* ln1_b   = (const float*)d_in[7];
    const float* w2_rel  = (const float*)d_in[8];
    const float* w2_root = (const float*)d_in[9];
    const float* b2      = (const float*)d_in[10];
    const float* ln2_g   = (const float*)d_in[11];
    const float* ln2_b   = (const float*)d_in[12];
    const float* cw1     = (const float*)d_in[13];
    const float* cb1     = (const float*)d_in[14];
    const float* cln1_g  = (const float*)d_in[15];
    const float* cln1_b  = (const float*)d_in[16];
    const float* cw2     = (const float*)d_in[17];
    const float* cb2     = (const float*)d_in[18];
    const float* cln2_g  = (const float*)d_in[19];
    const float* cln2_b  = (const float*)d_in[20];
    const float* cw3     = (const float*)d_in[21];
    const float* cb3     = (const float*)d_in[22];
    float* out = (float*)d_out;

    float *A, *X1, *X2, *H3, *H4;
    __nv_bfloat16* H;
    int *rowptr, *cur;
    unsigned* csr;
    cudaGetSymbolAddress((void**)&H,      g_H);
    cudaGetSymbolAddress((void**)&A,      g_A);
    cudaGetSymbolAddress((void**)&X1,     g_X1);
    cudaGetSymbolAddress((void**)&X2,     g_X2);
    cudaGetSymbolAddress((void**)&H3,     g_H3);
    cudaGetSymbolAddress((void**)&H4,     g_H4);
    cudaGetSymbolAddress((void**)&rowptr, g_rowptr);
    cudaGetSymbolAddress((void**)&cur,    g_cur);
    cudaGetSymbolAddress((void**)&csr,    g_csr);

    cudaFuncSetAttribute(mma_gemm4_k, cudaFuncAttributeMaxDynamicSharedMemorySize, MMA_SMEM4);
    cudaFuncSetAttribute(mma_gemm1_lngelu_k, cudaFuncAttributeMaxDynamicSharedMemorySize, MMA_SMEM1);

    const int gemmGrid = (NN + 127) / 128;   // 391
    const int rowGrid  = (NN + 7) / 8;       // 6250

    // ---- CSR build (by dst) ----
    zero_deg_k<<<(NN / 4 + 255) / 256, 256>>>(cur);
    hist_k<<<(NE / 4 + 255) / 256, 256>>>(ei, cur);
    scan_k<<<1, 1024>>>(cur, rowptr);
    fill_k<<<(NE / 4 + 255) / 256, 256>>>(ei, et, cur, csr);

    // ---- conv1 (aggr = add) ----
    mma_gemm4_k<<<gemmGrid, 512, MMA_SMEM4>>>(x, w1_root, w1_rel, b1, A, H, NN);
    gather_add_ln_k<<<rowGrid, 256>>>(rowptr, csr, A, H, ln1_g, ln1_b, X1);

    // ---- conv2 (aggr = per-relation max) ----
    mma_gemm4_k<<<gemmGrid, 512, MMA_SMEM4>>>(X1, w2_root, w2_rel, b2, A, H, NN);
    gather_max_ln_k<<<rowGrid, 256>>>(rowptr, csr, A, H, X1, ln2_g, ln2_b, X2);

    // ---- classifier (fused epilogues) ----
    mma_gemm1_lngelu_k<<<gemmGrid, 512, MMA_SMEM1>>>(X2, cw1, cb1, cln1_g, cln1_b, H3, NN);
    gemm_lngelu_k<<<gemmGrid, 256>>>(H3, cw2, cb2, cln2_g, cln2_b, H4, NN);
    gemm_logsoftmax_k<<<gemmGrid, 256>>>(H4, cw3, cb3, out, NN);
}

// round 17
// speedup vs baseline: 1.3761x; 1.0003x over previous
#include <cuda_runtime.h>
#include <cuda_bf16.h>
#include <cstdint>
#include <math.h>

#define NN   50000
#define NE   600000
#define HD   128
#define NREL 3
#define OUTD 40

// SMEM strides (floats) for conflict-free mma fragment loads:
#define SMA_STRIDE 132
#define SMB_STRIDE 136
#define MMA_SMEM4 ((128 * SMA_STRIDE + 2 * 128 * SMB_STRIDE) * 4)
#define MMA_SMEM1 ((128 * SMA_STRIDE + 128 * SMB_STRIDE) * 4)

// ---------------- scratch (device globals; no allocation) ----------------
static __device__ __nv_bfloat16 g_H [(size_t)NREL * NN * HD];   // relation outputs, bf16
static __device__ float g_A [(size_t)NN * HD];                  // root output, fp32
static __device__ float g_X1[(size_t)NN * HD];
static __device__ float g_X2[(size_t)NN * HD];
static __device__ float g_H3[(size_t)NN * HD];
static __device__ float g_H4[(size_t)NN * 64];
static __device__ int      g_rowptr[NN + 1];
static __device__ int      g_cur[NN];
static __device__ unsigned g_csr[NE];     // (type<<16) | src

// ---------------- helpers ----------------
__device__ __forceinline__ float wsum(float v) {
    #pragma unroll
    for (int o = 16; o > 0; o >>= 1) v += __shfl_xor_sync(0xFFFFFFFFu, v, o);
    return v;
}
__device__ __forceinline__ float hsum16(float v) {
    #pragma unroll
    for (int o = 8; o > 0; o >>= 1) v += __shfl_xor_sync(0xFFFFFFFFu, v, o);
    return v;
}
__device__ __forceinline__ float hmax16(float v) {
    #pragma unroll
    for (int o = 8; o > 0; o >>= 1) v = fmaxf(v, __shfl_xor_sync(0xFFFFFFFFu, v, o));
    return v;
}
__device__ __forceinline__ float to_tf32(float x) {
    unsigned r;
    asm("cvt.rna.tf32.f32 %0, %1;" : "=r"(r) : "f"(x));
    return __uint_as_float(r);
}
__device__ __forceinline__ void mma_tf32(float* c, const unsigned* a, const unsigned* b) {
    asm volatile(
        "mma.sync.aligned.m16n8k8.row.col.f32.tf32.tf32.f32 "
        "{%0,%1,%2,%3}, {%4,%5,%6,%7}, {%8,%9}, {%0,%1,%2,%3};"
        : "+f"(c[0]), "+f"(c[1]), "+f"(c[2]), "+f"(c[3])
        : "r"(a[0]), "r"(a[1]), "r"(a[2]), "r"(a[3]), "r"(b[0]), "r"(b[1]));
}
// load 4 bf16 (8 bytes) -> float4
__device__ __forceinline__ float4 ld_bf4(const __nv_bfloat16* p) {
    uint2 u = *(const uint2*)p;
    float2 lo = __bfloat1622float2(*(const __nv_bfloat162*)&u.x);
    float2 hi = __bfloat1622float2(*(const __nv_bfloat162*)&u.y);
    return make_float4(lo.x, lo.y, hi.x, hi.y);
}

// ================= MMA GEMM pieces (512 threads / 16 warps) =================
__device__ __forceinline__ void stage_A(const float* __restrict__ A, float* As,
                                        int row0, int N, int tid) {
    #pragma unroll
    for (int i = 0; i < 8; i++) {
        int idx = i * 512 + tid;
        int r = idx >> 5, c4 = (idx & 31) * 4;
        float4 v = make_float4(0.f, 0.f, 0.f, 0.f);
        if (row0 + r < N) v = *(const float4*)&A[(size_t)(row0 + r) * 128 + c4];
        v.x = to_tf32(v.x); v.y = to_tf32(v.y);
        v.z = to_tf32(v.z); v.w = to_tf32(v.w);
        *(float4*)&As[r * SMA_STRIDE + c4] = v;
    }
}
__device__ __forceinline__ void stage_B(const float* __restrict__ B, float* Bs, int tid) {
    #pragma unroll
    for (int i = 0; i < 8; i++) {
        int idx = i * 512 + tid;
        int k = idx >> 5, c4 = (idx & 31) * 4;
        float4 v = *(const float4*)&B[(size_t)k * 128 + c4];
        v.x = to_tf32(v.x); v.y = to_tf32(v.y);
        v.z = to_tf32(v.z); v.w = to_tf32(v.w);
        *(float4*)&Bs[k * SMB_STRIDE + c4] = v;
    }
}
__device__ __forceinline__ void copy_B_async(const float* __restrict__ B, float* Bs, int tid) {
    unsigned base = (unsigned)__cvta_generic_to_shared(Bs);
    #pragma unroll
    for (int i = 0; i < 8; i++) {
        int idx = i * 512 + tid;
        int k = idx >> 5, c4 = (idx & 31) * 4;
        asm volatile("cp.async.cg.shared.global [%0], [%1], 16;" ::
            "r"(base + (unsigned)((k * SMB_STRIDE + c4) * 4)),
            "l"(B + (size_t)k * 128 + c4) : "memory");
    }
}
__device__ __forceinline__ void acc_zero(float acc[2][4][4]) {
    #pragma unroll
    for (int mt = 0; mt < 2; mt++)
        #pragma unroll
        for (int nt = 0; nt < 4; nt++)
            #pragma unroll
            for (int q = 0; q < 4; q++) acc[mt][nt][q] = 0.f;
}
__device__ __forceinline__ void mma_compute_core(const float* As, const float* Bs,
                                                 int lane, int wm, int wn,
                                                 float acc[2][4][4], bool cvtB) {
    const float* Ab = As + (wm * 32 + (lane >> 2)) * SMA_STRIDE + (lane & 3);
    const float* Bb = Bs + (lane & 3) * SMB_STRIDE + wn * 32 + (lane >> 2);
    #pragma unroll
    for (int ks = 0; ks < 16; ks++) {
        unsigned a[2][4], b[4][2];
        #pragma unroll
        for (int mt = 0; mt < 2; mt++) {
            const float* p = Ab + mt * (16 * SMA_STRIDE) + ks * 8;
            a[mt][0] = __float_as_uint(p[0]);
            a[mt][1] = __float_as_uint(p[8 * SMA_STRIDE]);
            a[mt][2] = __float_as_uint(p[4]);
            a[mt][3] = __float_as_uint(p[8 * SMA_STRIDE + 4]);
        }
        #pragma unroll
        for (int nt = 0; nt < 4; nt++) {
            const float* p = Bb + ks * (8 * SMB_STRIDE) + nt * 8;
            if (cvtB) {
                b[nt][0] = __float_as_uint(to_tf32(p[0]));
                b[nt][1] = __float_as_uint(to_tf32(p[4 * SMB_STRIDE]));
            } else {
                b[nt][0] = __float_as_uint(p[0]);
                b[nt][1] = __float_as_uint(p[4 * SMB_STRIDE]);
            }
        }
        #pragma unroll
        for (int mt = 0; mt < 2; mt++)
            #pragma unroll
            for (int nt = 0; nt < 4; nt++)
                mma_tf32(acc[mt][nt], a[mt], b[nt]);
    }
}
__device__ __forceinline__ void mma_epilogue_f32(float acc[2][4][4],
                                                 const float* __restrict__ bias,
                                                 float* __restrict__ C,
                                                 int row0, int N, int lane, int wm, int wn) {
    #pragma unroll
    for (int nt = 0; nt < 4; nt++) {
        int c = wn * 32 + nt * 8 + (lane & 3) * 2;
        float b0 = bias ? bias[c] : 0.f;
        float b1 = bias ? bias[c + 1] : 0.f;
        #pragma unroll
        for (int mt = 0; mt < 2; mt++) {
            int r = row0 + wm * 32 + mt * 16 + (lane >> 2);
            float2 v0, v1;
            v0.x = acc[mt][nt][0] + b0; v0.y = acc[mt][nt][1] + b1;
            v1.x = acc[mt][nt][2] + b0; v1.y = acc[mt][nt][3] + b1;
            if (r < N)     *(float2*)&C[(size_t)r * 128 + c]       = v0;
            if (r + 8 < N) *(float2*)&C[(size_t)(r + 8) * 128 + c] = v1;
        }
    }
}
__device__ __forceinline__ void mma_epilogue_bf16(float acc[2][4][4],
                                                  __nv_bfloat16* __restrict__ C,
                                                  int row0, int N, int lane, int wm, int wn) {
    #pragma unroll
    for (int nt = 0; nt < 4; nt++) {
        int c = wn * 32 + nt * 8 + (lane & 3) * 2;
        #pragma unroll
        for (int mt = 0; mt < 2; mt++) {
            int r = row0 + wm * 32 + mt * 16 + (lane >> 2);
            __nv_bfloat162 w0 = __floats2bfloat162_rn(acc[mt][nt][0], acc[mt][nt][1]);
            __nv_bfloat162 w1 = __floats2bfloat162_rn(acc[mt][nt][2], acc[mt][nt][3]);
            if (r < N)     *(__nv_bfloat162*)&C[(size_t)r * 128 + c]       = w0;
            if (r + 8 < N) *(__nv_bfloat162*)&C[(size_t)(r + 8) * 128 + c] = w1;
        }
    }
}
__device__ __forceinline__ void mma_ln_act_epilogue(
    float acc[2][4][4], float* sm,
    const float* __restrict__ bias, const float* __restrict__ lg,
    const float* __restrict__ lb, float* __restrict__ C,
    int row0, int N, int lane, int wm, int wn, int act)
{
    float bc[4][2];
    #pragma unroll
    for (int nt = 0; nt < 4; nt++) {
        int c = wn * 32 + nt * 8 + (lane & 3) * 2;
        bc[nt][0] = bias[c]; bc[nt][1] = bias[c + 1];
    }
    float psA[2], pqA[2], psB[2], pqB[2];
    #pragma unroll
    for (int mt = 0; mt < 2; mt++) {
        float sA = 0.f, qA = 0.f, sB = 0.f, qB = 0.f;
        #pragma unroll
        for (int nt = 0; nt < 4; nt++) {
            float v0 = acc[mt][nt][0] + bc[nt][0];
            float v1 = acc[mt][nt][1] + bc[nt][1];
            float v2 = acc[mt][nt][2] + bc[nt][0];
            float v3 = acc[mt][nt][3] + bc[nt][1];
            sA += v0 + v1; qA += v0 * v0 + v1 * v1;
            sB += v2 + v3; qB += v2 * v2 + v3 * v3;
        }
        #pragma unroll
        for (int o = 1; o < 4; o <<= 1) {
            sA += __shfl_xor_sync(0xFFFFFFFFu, sA, o);
            qA += __shfl_xor_sync(0xFFFFFFFFu, qA, o);
            sB += __shfl_xor_sync(0xFFFFFFFFu, sB, o);
            qB += __shfl_xor_sync(0xFFFFFFFFu, qB, o);
        }
        psA[mt] = sA; pqA[mt] = qA; psB[mt] = sB; pqB[mt] = qB;
    }
    __syncthreads();
    float* S1 = sm;
    float* S2 = sm + 512;
    if ((lane & 3) == 0) {
        #pragma unroll
        for (int mt = 0; mt < 2; mt++) {
            int rA = wm * 32 + mt * 16 + (lane >> 2);
            S1[rA * 4 + wn] = psA[mt];        S2[rA * 4 + wn] = pqA[mt];
            S1[(rA + 8) * 4 + wn] = psB[mt];  S2[(rA + 8) * 4 + wn] = pqB[mt];
        }
    }
    __syncthreads();
    #pragma unroll
    for (int mt = 0; mt < 2; mt++) {
        int rlA = wm * 32 + mt * 16 + (lane >> 2);
        int rlB = rlA + 8;
        float sA = S1[rlA * 4 + 0] + S1[rlA * 4 + 1] + S1[rlA * 4 + 2] + S1[rlA * 4 + 3];
        float qA = S2[rlA * 4 + 0] + S2[rlA * 4 + 1] + S2[rlA * 4 + 2] + S2[rlA * 4 + 3];
        float sB = S1[rlB * 4 + 0] + S1[rlB * 4 + 1] + S1[rlB * 4 + 2] + S1[rlB * 4 + 3];
        float qB = S2[rlB * 4 + 0] + S2[rlB * 4 + 1] + S2[rlB * 4 + 2] + S2[rlB * 4 + 3];
        float mA = sA * (1.f / HD), mB = sB * (1.f / HD);
        float iA = rsqrtf(qA * (1.f / HD) - mA * mA + 1e-5f);
        float iB = rsqrtf(qB * (1.f / HD) - mB * mB + 1e-5f);
        #pragma unroll
        for (int nt = 0; nt < 4; nt++) {
            int c = wn * 32 + nt * 8 + (lane & 3) * 2;
            float g0 = lg[c], g1 = lg[c + 1], l0 = lb[c], l1 = lb[c + 1];
            float v0 = (acc[mt][nt][0] + bc[nt][0] - mA) * iA * g0 + l0;
            float v1 = (acc[mt][nt][1] + bc[nt][1] - mA) * iA * g1 + l1;
            float v2 = (acc[mt][nt][2] + bc[nt][0] - mB) * iB * g0 + l0;
            float v3 = (acc[mt][nt][3] + bc[nt][1] - mB) * iB * g1 + l1;
            if (act == 0) {
                v0 = fmaxf(v0, 0.f); v1 = fmaxf(v1, 0.f);
                v2 = fmaxf(v2, 0.f); v3 = fmaxf(v3, 0.f);
            } else {
                v0 = 0.5f * v0 * (1.f + erff(v0 * 0.70710678118654752f));
                v1 = 0.5f * v1 * (1.f + erff(v1 * 0.70710678118654752f));
                v2 = 0.5f * v2 * (1.f + erff(v2 * 0.70710678118654752f));
                v3 = 0.5f * v3 * (1.f + erff(v3 * 0.70710678118654752f));
            }
            int r = row0 + wm * 32 + mt * 16 + (lane >> 2);
            if (r < N)     { float2 w = {v0, v1}; *(float2*)&C[(size_t)r * 128 + c] = w; }
            if (r + 8 < N) { float2 w = {v2, v3}; *(float2*)&C[(size_t)(r + 8) * 128 + c] = w; }
        }
    }
}

// ---------------- conv 4-in-1 GEMM (512 threads, cp.async double-buffered B) ----------------
// root -> fp32 A; relations -> bf16 H
__global__ __launch_bounds__(512) void mma_gemm4_k(
    const float* __restrict__ A, const float* __restrict__ Broot,
    const float* __restrict__ Brel, const float* __restrict__ bias,
    float* __restrict__ Croot, __nv_bfloat16* __restrict__ Crel, int N)
{
    extern __shared__ float sm[];
    float* As  = sm;
    float* Bs0 = sm + 128 * SMA_STRIDE;
    float* Bs1 = Bs0 + 128 * SMB_STRIDE;

    const int tid  = threadIdx.x;
    const int row0 = blockIdx.x * 128;
    const int lane = tid & 31;
    const int wid  = tid >> 5;
    const int wm   = wid & 3;
    const int wn   = wid >> 2;

    copy_B_async(Broot, Bs0, tid);
    asm volatile("cp.async.commit_group;" ::: "memory");
    copy_B_async(Brel, Bs1, tid);
    asm volatile("cp.async.commit_group;" ::: "memory");
    stage_A(A, As, row0, N, tid);

    float acc[2][4][4];
    #pragma unroll
    for (int r = 0; r < 4; r++) {
        if (r == 3) asm volatile("cp.async.wait_group 0;" ::: "memory");
        else        asm volatile("cp.async.wait_group 1;" ::: "memory");
        __syncthreads();
        const float* Bs = (r & 1) ? Bs1 : Bs0;
        acc_zero(acc);
        mma_compute_core(As, Bs, lane, wm, wn, acc, true);
        if (r == 0)
            mma_epilogue_f32(acc, bias, Croot, row0, N, lane, wm, wn);
        else
            mma_epilogue_bf16(acc, Crel + (size_t)(r - 1) * NN * HD, row0, N, lane, wm, wn);
        __syncthreads();
        if (r < 2) {
            copy_B_async(Brel + (size_t)(r + 1) * (128 * 128), (r & 1) ? Bs1 : Bs0, tid);
            asm volatile("cp.async.commit_group;" ::: "memory");
        }
    }
}

// ---------------- cw1 GEMM with fused LN + exact GELU epilogue (512 threads) ----------------
__global__ __launch_bounds__(512) void mma_gemm1_lngelu_k(
    const float* __restrict__ A, const float* __restrict__ B,
    const float* __restrict__ bias, const float* __restrict__ lg,
    const float* __restrict__ lb, float* __restrict__ C, int N)
{
    extern __shared__ float sm[];
    float* As = sm;
    float* Bs = sm + 128 * SMA_STRIDE;

    const int tid  = threadIdx.x;
    const int row0 = blockIdx.x * 128;
    const int lane = tid & 31;
    const int wid  = tid >> 5;
    const int wm   = wid & 3;
    const int wn   = wid >> 2;

    stage_A(A, As, row0, N, tid);
    stage_B(B, Bs, tid);
    __syncthreads();
    float acc[2][4][4];
    acc_zero(acc);
    mma_compute_core(As, Bs, lane, wm, wn, acc, false);
    mma_ln_act_epilogue(acc, sm, bias, lg, lb, C, row0, N, lane, wm, wn, 1);
}

// ---------------- SIMT GEMM + fused LN+GELU (H3[128] @ cw2[128,64] -> H4) ----------------
__global__ __launch_bounds__(256) void gemm_lngelu_k(
    const float* __restrict__ A, const float* __restrict__ B,
    const float* __restrict__ bias, const float* __restrict__ lg,
    const float* __restrict__ lb, float* __restrict__ C, int N)
{
    const int K = 128, NC = 64;
    __shared__ float As[16][129];
    __shared__ float Bs[16][128];

    const int tid  = threadIdx.x;
    const int row0 = blockIdx.x * 128;
    const int tx   = tid & 15;
    const int ty   = tid >> 4;

    float acc[8][8];
    #pragma unroll
    for (int i = 0; i < 8; i++)
        #pragma unroll
        for (int j = 0; j < 8; j++) acc[i][j] = 0.f;

    for (int k0 = 0; k0 < K; k0 += 16) {
        #pragma unroll
        for (int p = 0; p < 2; p++) {
            int id = tid + p * 256;
            int r  = id >> 2;
            int kk = (id & 3) * 4;
            float4 v = make_float4(0.f, 0.f, 0.f, 0.f);
            int gr = row0 + r;
            if (gr < N) v = *(const float4*)&A[(size_t)gr * K + k0 + kk];
            As[kk + 0][r] = v.x; As[kk + 1][r] = v.y;
            As[kk + 2][r] = v.z; As[kk + 3][r] = v.w;
        }
        #pragma unroll
        for (int p = 0; p < 2; p++) {
            int id = tid + p * 256;
            int kk = id >> 5;
            int c  = (id & 31) * 4;
            float4 v = make_float4(0.f, 0.f, 0.f, 0.f);
            if (c + 3 < NC) v = *(const float4*)&B[(size_t)(k0 + kk) * NC + c];
            *(float4*)&Bs[kk][c] = v;
        }
        __syncthreads();
        #pragma unroll
        for (int kk = 0; kk < 16; kk++) {
            float a[8], b[8];
            #pragma unroll
            for (int i = 0; i < 8; i++) a[i] = As[kk][ty * 8 + i];
            #pragma unroll
            for (int j = 0; j < 8; j++) b[j] = Bs[kk][tx * 8 + j];
            #pragma unroll
            for (int i = 0; i < 8; i++)
                #pragma unroll
                for (int j = 0; j < 8; j++) acc[i][j] = fmaf(a[i], b[j], acc[i][j]);
        }
        __syncthreads();
    }

    const bool valid = (tx < 8);
    float bv[8], gv[8], lv[8];
    #pragma unroll
    for (int j = 0; j < 8; j++) {
        int c = tx * 8 + j;
        bv[j] = valid ? bias[c] : 0.f;
        gv[j] = valid ? lg[c]   : 0.f;
        lv[j] = valid ? lb[c]   : 0.f;
    }
    #pragma unroll
    for (int i = 0; i < 8; i++) {
        float s = 0.f, q = 0.f;
        #pragma unroll
        for (int j = 0; j < 8; j++) {
            float v = acc[i][j] + bv[j];
            acc[i][j] = v;
            if (valid) { s += v; q += v * v; }
        }
        s = hsum16(s); q = hsum16(q);
        float mean = s * (1.f / 64.f);
        float inv  = rsqrtf(q * (1.f / 64.f) - mean * mean + 1e-5f);
        int gr = row0 + ty * 8 + i;
        if (valid && gr < N) {
            #pragma unroll
            for (int j = 0; j < 8; j++) {
                float y = (acc[i][j] - mean) * inv * gv[j] + lv[j];
                y = 0.5f * y * (1.f + erff(y * 0.70710678118654752f));
                C[(size_t)gr * 64 + tx * 8 + j] = y;
            }
        }
    }
}

// ---------------- SIMT GEMM + fused log_softmax (H4[64] @ cw3[64,40] -> out) ----------------
__global__ __launch_bounds__(256) void gemm_logsoftmax_k(
    const float* __restrict__ A, const float* __restrict__ B,
    const float* __restrict__ bias, float* __restrict__ C, int N)
{
    const int K = 64, NC = OUTD;
    __shared__ float As[16][129];
    __shared__ float Bs[16][128];

    const int tid  = threadIdx.x;
    const int row0 = blockIdx.x * 128;
    const int tx   = tid & 15;
    const int ty   = tid >> 4;

    float acc[8][8];
    #pragma unroll
    for (int i = 0; i < 8; i++)
        #pragma unroll
        for (int j = 0; j < 8; j++) acc[i][j] = 0.f;

    for (int k0 = 0; k0 < K; k0 += 16) {
        #pragma unroll
        for (int p = 0; p < 2; p++) {
            int id = tid + p * 256;
            int r  = id >> 2;
            int kk = (id & 3) * 4;
            float4 v = make_float4(0.f, 0.f, 0.f, 0.f);
            int gr = row0 + r;
            if (gr < N) v = *(const float4*)&A[(size_t)gr * K + k0 + kk];
            As[kk + 0][r] = v.x; As[kk + 1][r] = v.y;
            As[kk + 2][r] = v.z; As[kk + 3][r] = v.w;
        }
        #pragma unroll
        for (int p = 0; p < 2; p++) {
            int id = tid + p * 256;
            int kk = id >> 5;
            int c  = (id & 31) * 4;
            float4 v = make_float4(0.f, 0.f, 0.f, 0.f);
            if (c + 3 < NC) v = *(const float4*)&B[(size_t)(k0 + kk) * NC + c];
            *(float4*)&Bs[kk][c] = v;
        }
        __syncthreads();
        #pragma unroll
        for (int kk = 0; kk < 16; kk++) {
            float a[8], b[8];
            #pragma unroll
            for (int i = 0; i < 8; i++) a[i] = As[kk][ty * 8 + i];
            #pragma unroll
            for (int j = 0; j < 8; j++) b[j] = Bs[kk][tx * 8 + j];
            #pragma unroll
            for (int i = 0; i < 8; i++)
                #pragma unroll
                for (int j = 0; j < 8; j++) acc[i][j] = fmaf(a[i], b[j], acc[i][j]);
        }
        __syncthreads();
    }

    const bool valid = (tx < 5);
    float bv[8];
    #pragma unroll
    for (int j = 0; j < 8; j++) {
        int c = tx * 8 + j;
        bv[j] = (c < NC) ? bias[c] : 0.f;
    }
    #pragma unroll
    for (int i = 0; i < 8; i++) {
        float m = -INFINITY;
        #pragma unroll
        for (int j = 0; j < 8; j++) {
            float v = acc[i][j] + bv[j];
            acc[i][j] = v;
            if (valid) m = fmaxf(m, v);
        }
        m = hmax16(m);
        float s = 0.f;
        if (valid) {
            #pragma unroll
            for (int j = 0; j < 8; j++) s += expf(acc[i][j] - m);
        }
        s = hsum16(s);
        float ls = m + logf(s);
        int gr = row0 + ty * 8 + i;
        if (valid && gr < N) {
            #pragma unroll
            for (int j = 0; j < 8; j++)
                C[(size_t)gr * NC + tx * 8 + j] = acc[i][j] - ls;
        }
    }
}

// ================= CSR build =================
__global__ void zero_deg_k(int* __restrict__ cur)
{
    int i = blockIdx.x * blockDim.x + threadIdx.x;
    if (i * 4 < NN) {
        int4 z = make_int4(0, 0, 0, 0);
        if (i * 4 + 3 < NN) ((int4*)cur)[i] = z;
        else for (int j = i * 4; j < NN; j++) cur[j] = 0;
    }
}
__global__ void hist_k(const int* __restrict__ ei, int* __restrict__ cur)
{
    int e4 = blockIdx.x * blockDim.x + threadIdx.x;
    if (e4 * 4 >= NE) return;
    int4 d = ((const int4*)(ei + NE))[e4];
    atomicAdd(&cur[d.x], 1);
    atomicAdd(&cur[d.y], 1);
    atomicAdd(&cur[d.z], 1);
    atomicAdd(&cur[d.w], 1);
}
__global__ __launch_bounds__(1024) void scan_k(int* __restrict__ cur, int* __restrict__ rowptr)
{
    __shared__ int part[1024];
    const int t = threadIdx.x;
    const int CH = (NN + 1023) / 1024;
    int base = t * CH;
    int s = 0;
    for (int i = 0; i < CH; i++) {
        int idx = base + i;
        if (idx < NN) s += cur[idx];
    }
    part[t] = s;
    __syncthreads();
    for (int off = 1; off < 1024; off <<= 1) {
        int v = 0;
        if (t >= off) v = part[t - off];
        __syncthreads();
        if (t >= off) part[t] += v;
        __syncthreads();
    }
    int run = (t == 0) ? 0 : part[t - 1];
    for (int i = 0; i < CH; i++) {
        int idx = base + i;
        if (idx < NN) {
            int d = cur[idx];
            rowptr[idx] = run;
            cur[idx] = run;
            run += d;
        }
    }
    if (t == 1023) rowptr[NN] = part[1023];
}
__global__ void fill_k(const int* __restrict__ ei, const int* __restrict__ et,
                       int* __restrict__ cur, unsigned* __restrict__ csr)
{
    int e4 = blockIdx.x * blockDim.x + threadIdx.x;
    if (e4 * 4 >= NE) return;
    int4 s = ((const int4*)ei)[e4];
    int4 d = ((const int4*)(ei + NE))[e4];
    int4 t = ((const int4*)et)[e4];
    csr[atomicAdd(&cur[d.x], 1)] = (unsigned)s.x | ((unsigned)t.x << 16);
    csr[atomicAdd(&cur[d.y], 1)] = (unsigned)s.y | ((unsigned)t.y << 16);
    csr[atomicAdd(&cur[d.z], 1)] = (unsigned)s.z | ((unsigned)t.z << 16);
    csr[atomicAdd(&cur[d.w], 1)] = (unsigned)s.w | ((unsigned)t.w << 16);
}

// ================= conv1 gather: sum over bf16 H, fused LN+ReLU =================
__global__ __launch_bounds__(256) void gather_add_ln_k(
    const int* __restrict__ rowptr, const unsigned* __restrict__ csr,
    const float* __restrict__ A, const __nv_bfloat16* __restrict__ H,
    const float* __restrict__ g, const float* __restrict__ b,
    float* __restrict__ X1)
{
    int row = blockIdx.x * 8 + (threadIdx.x >> 5);
    if (row >= NN) return;
    int lane = threadIdx.x & 31;
    size_t base = (size_t)row * HD + lane * 4;

    float4 acc = *(const float4*)&A[base];
    int e0 = rowptr[row], e1 = rowptr[row + 1];
    int e = e0;
    for (; e + 3 < e1; e += 4) {
        unsigned p0 = __ldg(&csr[e]),     p1 = __ldg(&csr[e + 1]);
        unsigned p2 = __ldg(&csr[e + 2]), p3 = __ldg(&csr[e + 3]);
        const float4 v0 = ld_bf4(&H[((size_t)(p0 >> 16) * NN + (p0 & 0xFFFFu)) * HD + lane * 4]);
        const float4 v1 = ld_bf4(&H[((size_t)(p1 >> 16) * NN + (p1 & 0xFFFFu)) * HD + lane * 4]);
        const float4 v2 = ld_bf4(&H[((size_t)(p2 >> 16) * NN + (p2 & 0xFFFFu)) * HD + lane * 4]);
        const float4 v3 = ld_bf4(&H[((size_t)(p3 >> 16) * NN + (p3 & 0xFFFFu)) * HD + lane * 4]);
        acc.x += (v0.x + v1.x) + (v2.x + v3.x);
        acc.y += (v0.y + v1.y) + (v2.y + v3.y);
        acc.z += (v0.z + v1.z) + (v2.z + v3.z);
        acc.w += (v0.w + v1.w) + (v2.w + v3.w);
    }
    for (; e < e1; e++) {
        unsigned p0 = __ldg(&csr[e]);
        const float4 v0 = ld_bf4(&H[((size_t)(p0 >> 16) * NN + (p0 & 0xFFFFu)) * HD + lane * 4]);
        acc.x += v0.x; acc.y += v0.y; acc.z += v0.z; acc.w += v0.w;
    }

    float s  = acc.x + acc.y + acc.z + acc.w;
    float q  = acc.x * acc.x + acc.y * acc.y + acc.z * acc.z + acc.w * acc.w;
    s = wsum(s); q = wsum(q);
    float mean = s * (1.f / HD);
    float inv  = rsqrtf(q * (1.f / HD) - mean * mean + 1e-5f);
    int c = lane * 4;
    float4 y;
    y.x = fmaxf((acc.x - mean) * inv * g[c + 0] + b[c + 0], 0.f);
    y.y = fmaxf((acc.y - mean) * inv * g[c + 1] + b[c + 1], 0.f);
    y.z = fmaxf((acc.z - mean) * inv * g[c + 2] + b[c + 2], 0.f);
    y.w = fmaxf((acc.w - mean) * inv * g[c + 3] + b[c + 3], 0.f);
    *(float4*)&X1[base] = y;
}

// ================= conv2 gather: per-relation max over bf16 H, fused LN+ReLU+res =================
__global__ __launch_bounds__(256) void gather_max_ln_k(
    const int* __restrict__ rowptr, const unsigned* __restrict__ csr,
    const float* __restrict__ A, const __nv_bfloat16* __restrict__ H,
    const float* __restrict__ X1, const float* __restrict__ g,
    const float* __restrict__ b, float* __restrict__ X2)
{
    int row = blockIdx.x * 8 + (threadIdx.x >> 5);
    if (row >= NN) return;
    int lane = threadIdx.x & 31;
    size_t base = (size_t)row * HD + lane * 4;

    float4 acc = *(const float4*)&A[base];
    float4 m0 = make_float4(-INFINITY, -INFINITY, -INFINITY, -INFINITY);
    float4 m1 = m0, m2 = m0;

    int e0 = rowptr[row], e1 = rowptr[row + 1];
    int e = e0;
    for (; e + 1 < e1; e += 2) {
        unsigned p0 = __ldg(&csr[e]), p1 = __ldg(&csr[e + 1]);
        int t0 = p0 >> 16, t1 = p1 >> 16;
        const float4 v0 = ld_bf4(&H[((size_t)t0 * NN + (p0 & 0xFFFFu)) * HD + lane * 4]);
        const float4 v1 = ld_bf4(&H[((size_t)t1 * NN + (p1 & 0xFFFFu)) * HD + lane * 4]);
        if (t0 == 0) { m0.x = fmaxf(m0.x, v0.x); m0.y = fmaxf(m0.y, v0.y); m0.z = fmaxf(m0.z, v0.z); m0.w = fmaxf(m0.w, v0.w); }
        else if (t0 == 1) { m1.x = fmaxf(m1.x, v0.x); m1.y = fmaxf(m1.y, v0.y); m1.z = fmaxf(m1.z, v0.z); m1.w = fmaxf(m1.w, v0.w); }
        else { m2.x = fmaxf(m2.x, v0.x); m2.y = fmaxf(m2.y, v0.y); m2.z = fmaxf(m2.z, v0.z); m2.w = fmaxf(m2.w, v0.w); }
        if (t1 == 0) { m0.x = fmaxf(m0.x, v1.x); m0.y = fmaxf(m0.y, v1.y); m0.z = fmaxf(m0.z, v1.z); m0.w = fmaxf(m0.w, v1.w); }
        else if (t1 == 1) { m1.x = fmaxf(m1.x, v1.x); m1.y = fmaxf(m1.y, v1.y); m1.z = fmaxf(m1.z, v1.z); m1.w = fmaxf(m1.w, v1.w); }
        else { m2.x = fmaxf(m2.x, v1.x); m2.y = fmaxf(m2.y, v1.y); m2.z = fmaxf(m2.z, v1.z); m2.w = fmaxf(m2.w, v1.w); }
    }
    if (e < e1) {
        unsigned p = __ldg(&csr[e]);
        int t = p >> 16;
        const float4 v = ld_bf4(&H[((size_t)t * NN + (p & 0xFFFFu)) * HD + lane * 4]);
        if (t == 0) { m0.x = fmaxf(m0.x, v.x); m0.y = fmaxf(m0.y, v.y); m0.z = fmaxf(m0.z, v.z); m0.w = fmaxf(m0.w, v.w); }
        else if (t == 1) { m1.x = fmaxf(m1.x, v.x); m1.y = fmaxf(m1.y, v.y); m1.z = fmaxf(m1.z, v.z); m1.w = fmaxf(m1.w, v.w); }
        else { m2.x = fmaxf(m2.x, v.x); m2.y = fmaxf(m2.y, v.y); m2.z = fmaxf(m2.z, v.z); m2.w = fmaxf(m2.w, v.w); }
    }
    acc.x += (m0.x > -INFINITY ? m0.x : 0.f) + (m1.x > -INFINITY ? m1.x : 0.f) + (m2.x > -INFINITY ? m2.x : 0.f);
    acc.y += (m0.y > -INFINITY ? m0.y : 0.f) + (m1.y > -INFINITY ? m1.y : 0.f) + (m2.y > -INFINITY ? m2.y : 0.f);
    acc.z += (m0.z > -INFINITY ? m0.z : 0.f) + (m1.z > -INFINITY ? m1.z : 0.f) + (m2.z > -INFINITY ? m2.z : 0.f);
    acc.w += (m0.w > -INFINITY ? m0.w : 0.f) + (m1.w > -INFINITY ? m1.w : 0.f) + (m2.w > -INFINITY ? m2.w : 0.f);

    float s = acc.x + acc.y + acc.z + acc.w;
    float q = acc.x * acc.x + acc.y * acc.y + acc.z * acc.z + acc.w * acc.w;
    s = wsum(s); q = wsum(q);
    float mean = s * (1.f / HD);
    float inv  = rsqrtf(q * (1.f / HD) - mean * mean + 1e-5f);
    float4 x1v = *(const float4*)&X1[base];
    int c = lane * 4;
    float4 y;
    y.x = fmaxf((acc.x - mean) * inv * g[c + 0] + b[c + 0], 0.f) + 0.2f * x1v.x;
    y.y = fmaxf((acc.y - mean) * inv * g[c + 1] + b[c + 1], 0.f) + 0.2f * x1v.y;
    y.z = fmaxf((acc.z - mean) * inv * g[c + 2] + b[c + 2], 0.f) + 0.2f * x1v.z;
    y.w = fmaxf((acc.w - mean) * inv * g[c + 3] + b[c + 3], 0.f) + 0.2f * x1v.w;
    *(float4*)&X2[base] = y;
}

// ---------------- host launcher ----------------
extern "C" void kernel_launch(void* const* d_in, const int* in_sizes, int n_in,
                              void* d_out, int out_size)
{
    const float* x       = (const float*)d_in[0];
    const int*   ei      = (const int*)  d_in[1];
    const int*   et      = (const int*)  d_in[2];
    const float* w1_rel  = (const float*)d_in[3];
    const float* w1_root = (const float*)d_in[4];
    const float* b1      = (const float*)d_in[5];
    const float* ln1_g   = (const float*)d_in[6];
    const float* ln1_b   = (const float*)d_in[7];
    const float* w2_rel  = (const float*)d_in[8];
    const float* w2_root = (const float*)d_in[9];
    const float* b2      = (const float*)d_in[10];
    const float* ln2_g   = (const float*)d_in[11];
    const float* ln2_b   = (const float*)d_in[12];
    const float* cw1     = (const float*)d_in[13];
    const float* cb1     = (const float*)d_in[14];
    const float* cln1_g  = (const float*)d_in[15];
    const float* cln1_b  = (const float*)d_in[16];
    const float* cw2     = (const float*)d_in[17];
    const float* cb2     = (const float*)d_in[18];
    const float* cln2_g  = (const float*)d_in[19];
    const float* cln2_b  = (const float*)d_in[20];
    const float* cw3     = (const float*)d_in[21];
    const float* cb3     = (const float*)d_in[22];
    float* out = (float*)d_out;

    float *A, *X1, *X2, *H3, *H4;
    __nv_bfloat16* H;
    int *rowptr, *cur;
    unsigned* csr;
    cudaGetSymbolAddress((void**)&H,      g_H);
    cudaGetSymbolAddress((void**)&A,      g_A);
    cudaGetSymbolAddress((void**)&X1,     g_X1);
    cudaGetSymbolAddress((void**)&X2,     g_X2);
    cudaGetSymbolAddress((void**)&H3,     g_H3);
    cudaGetSymbolAddress((void**)&H4,     g_H4);
    cudaGetSymbolAddress((void**)&rowptr, g_rowptr);
    cudaGetSymbolAddress((void**)&cur,    g_cur);
    cudaGetSymbolAddress((void**)&csr,    g_csr);

    cudaFuncSetAttribute(mma_gemm4_k, cudaFuncAttributeMaxDynamicSharedMemorySize, MMA_SMEM4);
    cudaFuncSetAttribute(mma_gemm1_lngelu_k, cudaFuncAttributeMaxDynamicSharedMemorySize, MMA_SMEM1);

    const int gemmGrid = (NN + 127) / 128;   // 391
    const int rowGrid  = (NN + 7) / 8;       // 6250

    // ---- CSR build (by dst) ----
    zero_deg_k<<<(NN / 4 + 255) / 256, 256>>>(cur);
    hist_k<<<(NE / 4 + 255) / 256, 256>>>(ei, cur);
    scan_k<<<1, 1024>>>(cur, rowptr);
    fill_k<<<(NE / 4 + 255) / 256, 256>>>(ei, et, cur, csr);

    // ---- conv1 (aggr = add) ----
    mma_gemm4_k<<<gemmGrid, 512, MMA_SMEM4>>>(x, w1_root, w1_rel, b1, A, H, NN);
    gather_add_ln_k<<<rowGrid, 256>>>(rowptr, csr, A, H, ln1_g, ln1_b, X1);

    // ---- conv2 (aggr = per-relation max) ----
    mma_gemm4_k<<<gemmGrid, 512, MMA_SMEM4>>>(X1, w2_root, w2_rel, b2, A, H, NN);
    gather_max_ln_k<<<rowGrid, 256>>>(rowptr, csr, A, H, X1, ln2_g, ln2_b, X2);

    // ---- classifier (fused epilogues) ----
    mma_gemm1_lngelu_k<<<gemmGrid, 512, MMA_SMEM1>>>(X2, cw1, cb1, cln1_g, cln1_b, H3, NN);
    gemm_lngelu_k<<<gemmGrid, 256>>>(H3, cw2, cb2, cln2_g, cln2_b, H4, NN);
    gemm_logsoftmax_k<<<gemmGrid, 256>>>(H4, cw3, cb3, out, NN);
}